// round 7
// baseline (speedup 1.0000x reference)
#include <cuda_runtime.h>
#include <cstdint>

#define Bq 16
#define Cq 512
#define Nq 4096
#define Kq 64

// ================= scratch (static device allocations only) =================
__device__ float2 gWh2[64][512];      // per-chunk W-hi images: [chunk][k*8+pp] = (W1h, W2h)
__device__ float2 gWl2[64][512];      // W-lo images
__device__ float gInvS[Kq][Cq];
__device__ float gCst[Kq];
__device__ float g_sa[(size_t)Bq*Kq*Nq];
__device__ float g_wx8[8][Bq][Kq][Cq];
__device__ float g_wsum[Bq][Kq];
__device__ float g_row[Bq][Kq];
__device__ float g_nodes[Bq][Kq][Cq];

// ================= helpers =================
__device__ __forceinline__ float tf32hi(float v) {
    return __uint_as_float(__float_as_uint(v) & 0xFFFFE000u);
}
// 3-bit pair-swizzle keyed on row bits 1..3
__device__ __forceinline__ int swz(int row) {
    return (((row >> 1) & 1) << 2) | (((row >> 2) & 1) << 1) | ((row >> 3) & 1);
}
__device__ __forceinline__ void mma8(float* d, const unsigned* a, const unsigned* b) {
    asm volatile(
        "mma.sync.aligned.m16n8k8.row.col.f32.tf32.tf32.f32 "
        "{%0,%1,%2,%3}, {%4,%5,%6,%7}, {%8,%9}, {%0,%1,%2,%3};"
        : "+f"(d[0]), "+f"(d[1]), "+f"(d[2]), "+f"(d[3])
        : "r"(a[0]), "r"(a[1]), "r"(a[2]), "r"(a[3]), "r"(b[0]), "r"(b[1]));
}

// smem per buffer: A-hi [256 rows][8 float2], A-lo, B-hi [64][8 float2], B-lo
#define BUF     40960
#define OFF_FH  0
#define OFF_FL  16384
#define OFF_WH  32768
#define OFF_WL  36864
#define P_SMEM  81920

// one 2-step chunk (16 reduction slots), warp tile 32(row) x 64(col), 3xTF32.
// Pass-major in 4-j batches: same-acc MMA dependency distance = 8 issues.
// Per-acc accumulation order (hh -> hl -> lh per step) identical to prior rounds.
__device__ __forceinline__ void gemm_chunk(const char* bufp, int rowbase, int g, int q,
                                           float acc[2][8][4]) {
    const float2* fh = (const float2*)(bufp + OFF_FH);
    const float2* fl = (const float2*)(bufp + OFF_FL);
    const float2* wh = (const float2*)(bufp + OFF_WH);
    const float2* wl = (const float2*)(bufp + OFF_WL);
#pragma unroll
    for (int s = 0; s < 2; ++s) {
        const int p = (s << 2) + q;
        unsigned ah[2][4], al[2][4];
#pragma unroll
        for (int i = 0; i < 2; ++i) {
            int r0 = rowbase + (i << 4) + g;
            int r1 = r0 + 8;
            float2 t0 = fh[r0 * 8 + (p ^ swz(r0))];
            float2 t1 = fh[r1 * 8 + (p ^ swz(r1))];
            ah[i][0] = __float_as_uint(t0.x); ah[i][2] = __float_as_uint(t0.y);
            ah[i][1] = __float_as_uint(t1.x); ah[i][3] = __float_as_uint(t1.y);
            float2 u0 = fl[r0 * 8 + (p ^ swz(r0))];
            float2 u1 = fl[r1 * 8 + (p ^ swz(r1))];
            al[i][0] = __float_as_uint(u0.x); al[i][2] = __float_as_uint(u0.y);
            al[i][1] = __float_as_uint(u1.x); al[i][3] = __float_as_uint(u1.y);
        }
#pragma unroll
        for (int jb = 0; jb < 2; ++jb) {
            unsigned bh[4][2], bl[4][2];
#pragma unroll
            for (int jj = 0; jj < 4; ++jj) {
                int k = (((jb << 2) + jj) << 3) + g;
                float2 bhv = wh[k * 8 + (p ^ swz(k))];
                float2 blv = wl[k * 8 + (p ^ swz(k))];
                bh[jj][0] = __float_as_uint(bhv.x); bh[jj][1] = __float_as_uint(bhv.y);
                bl[jj][0] = __float_as_uint(blv.x); bl[jj][1] = __float_as_uint(blv.y);
            }
#pragma unroll
            for (int jj = 0; jj < 4; ++jj)
#pragma unroll
                for (int i = 0; i < 2; ++i)
                    mma8(acc[i][(jb << 2) + jj], ah[i], bh[jj]);
#pragma unroll
            for (int jj = 0; jj < 4; ++jj)
#pragma unroll
                for (int i = 0; i < 2; ++i)
                    mma8(acc[i][(jb << 2) + jj], ah[i], bl[jj]);
#pragma unroll
            for (int jj = 0; jj < 4; ++jj)
#pragma unroll
                for (int i = 0; i < 2; ++i)
                    mma8(acc[i][(jb << 2) + jj], al[i], bh[jj]);
        }
    }
}

// ================= prep: sigma, W images, const =================
__global__ void prep_kernel(const float* __restrict__ anchor,
                            const float* __restrict__ sraw) {
    const int k = blockIdx.x;       // 64
    const int tid = threadIdx.x;    // 256
    float part = 0.f;
#pragma unroll
    for (int j = 0; j < 2; ++j) {
        int c = tid + j * 256;
        float sr = sraw[k * Cq + c];
        float sg = 1.f / (1.f + __expf(-sr));
        float a  = anchor[k * Cq + c];
        float i2 = 1.f / (sg * sg);
        float w2 = -2.f * a * i2;
        gInvS[k][c] = 1.f / sg;
        part += a * a * i2;
        int ch = c >> 3, p = c & 7;
        int pp = p ^ swz(k);
        float i2h = tf32hi(i2), w2h = tf32hi(w2);
        gWh2[ch][k * 8 + pp] = make_float2(i2h, w2h);
        gWl2[ch][k * 8 + pp] = make_float2(i2 - i2h, w2 - w2h);
    }
#pragma unroll
    for (int off = 16; off; off >>= 1) part += __shfl_xor_sync(0xffffffffu, part, off);
    __shared__ float red[8];
    if ((tid & 31) == 0) red[tid >> 5] = part;
    __syncthreads();
    if (tid == 0) {
        float s = 0.f;
#pragma unroll
        for (int i = 0; i < 8; ++i) s += red[i];
        gCst[k] = s;
    }
}

// ================= phase 1: distance GEMM (3xTF32 mma) + softmax =================
// block = (n-tile 256, b). warp tile 32n x 64k. 64 chunks of 8 c (16 c2 slots).
// Software pipeline: LDG prefetch one chunk ahead of the smem store stage.
__global__ __launch_bounds__(256, 2)
void phase1_kernel(const float* __restrict__ x, float* __restrict__ sa) {
    extern __shared__ char smem[];
    __shared__ float cst[64];
    const int tid = threadIdx.x;
    const int w = tid >> 5, lane = tid & 31;
    const int g = lane >> 2, q = lane & 3;
    const int n0w = w << 5;
    const int b  = blockIdx.y;
    const int n0 = blockIdx.x << 8;
    const float* xb = x + (size_t)b * Cq * Nq + n0;
    if (tid < 64) cst[tid] = gCst[tid];

    float acc[2][8][4];
#pragma unroll
    for (int i = 0; i < 2; ++i)
#pragma unroll
        for (int j = 0; j < 8; ++j)
#pragma unroll
            for (int e = 0; e < 4; ++e) acc[i][j][e] = 0.f;

    const int sz_n = swz(tid);
    float   xr[8];              // prefetched x values (chunk+1)
    float4  wrh, wrl;           // prefetched W image rows

    auto ldA = [&](int ch) {
        const float* xp = xb + (size_t)(ch << 3) * Nq + tid;
#pragma unroll
        for (int cl = 0; cl < 8; ++cl) xr[cl] = __ldg(xp + (size_t)cl * Nq);
        wrh = ((const float4*)&gWh2[ch][0])[tid];
        wrl = ((const float4*)&gWl2[ch][0])[tid];
    };
    auto stA = [&](int buf) {
        char* bp = smem + buf * BUF;
        ((float4*)(bp + OFF_WH))[tid] = wrh;
        ((float4*)(bp + OFF_WL))[tid] = wrl;
        float2* fh = (float2*)(bp + OFF_FH);
        float2* fl = (float2*)(bp + OFF_FL);
#pragma unroll
        for (int cl = 0; cl < 8; ++cl) {
            float v = xr[cl];
            float v2 = v * v;
            float vh = tf32hi(v),  vl = v - vh;
            float qh = tf32hi(v2), ql = v2 - qh;
            int pp = cl ^ sz_n;
            fh[tid * 8 + pp] = make_float2(qh, vh);   // slot q = x^2, slot q+4 = x
            fl[tid * 8 + pp] = make_float2(ql, vl);
        }
    };

    ldA(0); stA(0); ldA(1);
    __syncthreads();
    for (int ch = 0; ch < 64; ++ch) {
        if (ch + 1 < 64) stA((ch + 1) & 1);
        if (ch + 2 < 64) ldA(ch + 2);
        gemm_chunk(smem + (ch & 1) * BUF, n0w, g, q, acc);
        __syncthreads();
    }

    // stage d2 in smem (overlays buffers)
    float* d2 = (float*)smem;
#pragma unroll
    for (int i = 0; i < 2; ++i) {
        int r0 = n0w + (i << 4) + g;
#pragma unroll
        for (int j = 0; j < 8; ++j) {
            int kc = (j << 3) + (q << 1);
            *(float2*)&d2[r0 * 66 + kc]       = make_float2(acc[i][j][0], acc[i][j][1]);
            *(float2*)&d2[(r0 + 8) * 66 + kc] = make_float2(acc[i][j][2], acc[i][j][3]);
        }
    }
    __syncthreads();

    // softmax: one thread per n
    {
        float e[64];
#pragma unroll
        for (int k = 0; k < 64; ++k) e[k] = d2[tid * 66 + k] + cst[k];
        float mn = e[0];
#pragma unroll
        for (int k = 1; k < 64; ++k) mn = fminf(mn, e[k]);
        float s = 0.f;
#pragma unroll
        for (int k = 0; k < 64; ++k) {
            float t = __expf(-0.5f * (e[k] - mn));
            e[k] = t;
            s += t;
        }
        float r = 1.f / s;
        float* sp = sa + (size_t)b * Kq * Nq + n0 + tid;
#pragma unroll
        for (int k = 0; k < 64; ++k) sp[(size_t)k * Nq] = e[k] * r;
    }
}

// ================= w_sum =================
__global__ void wsum_kernel(const float* __restrict__ sa) {
    const int bk = blockIdx.x;      // 1024
    const int tid = threadIdx.x;    // 256
    const float4* row = reinterpret_cast<const float4*>(sa + (size_t)bk * Nq);
    float s = 0.f;
#pragma unroll
    for (int i = 0; i < 4; ++i) {
        float4 v = row[tid + i * 256];
        s += (v.x + v.y) + (v.z + v.w);
    }
#pragma unroll
    for (int off = 16; off; off >>= 1) s += __shfl_xor_sync(0xffffffffu, s, off);
    __shared__ float red[8];
    if ((tid & 31) == 0) red[tid >> 5] = s;
    __syncthreads();
    if (tid == 0) {
        float t = 0.f;
#pragma unroll
        for (int i = 0; i < 8; ++i) t += red[i];
        g_wsum[bk >> 6][bk & 63] = t;
    }
}

// ================= phase 2: wx[c,k] = sum_n x[c,n]*sa[k,n] (3xTF32 mma) =================
// grid (2 ctile, 16 b, 8 seg). block tile 256c x 64k, 32 chunks of 16 n.
// Same software pipeline as phase 1.
__global__ __launch_bounds__(256, 2)
void phase2_kernel(const float* __restrict__ x, const float* __restrict__ sa) {
    extern __shared__ char smem[];
    const int tid = threadIdx.x;
    const int w = tid >> 5, lane = tid & 31;
    const int g = lane >> 2, q = lane & 3;
    const int c0w = w << 5;
    const int c0 = (int)blockIdx.x << 8;
    const int b  = blockIdx.y;
    const int seg = blockIdx.z;
    const int n0 = seg << 9;
    const float* xb = x  + ((size_t)b * Cq + c0) * Nq + n0;
    const float* sb = sa + (size_t)b * Kq * Nq + n0;

    float acc[2][8][4];
#pragma unroll
    for (int i = 0; i < 2; ++i)
#pragma unroll
        for (int j = 0; j < 8; ++j)
#pragma unroll
            for (int e = 0; e < 4; ++e) acc[i][j][e] = 0.f;

    const int n4 = (tid & 3) << 2;
    const int crow = tid >> 2;
    float4 xr4[4];
    float4 sr4;

    auto ldA = [&](int ch) {
        const int nn = ch << 4;
#pragma unroll
        for (int pz = 0; pz < 4; ++pz) {
            int cc = crow + (pz << 6);
            xr4[pz] = *(const float4*)(xb + (size_t)cc * Nq + nn + n4);
        }
        sr4 = *(const float4*)(sb + (size_t)crow * Nq + nn + n4);
    };
    auto stA = [&](int buf) {
        char* bp = smem + buf * BUF;
        float* aH = (float*)(bp + OFF_FH);
        float* aL = (float*)(bp + OFF_FL);
        float* bH = (float*)(bp + OFF_WH);
        float* bL = (float*)(bp + OFF_WL);
#pragma unroll
        for (int pz = 0; pz < 4; ++pz) {
            int cc = crow + (pz << 6);
            float vv[4] = { xr4[pz].x, xr4[pz].y, xr4[pz].z, xr4[pz].w };
            int sz = swz(cc);
#pragma unroll
            for (int e = 0; e < 4; ++e) {
                int nl = n4 + e;
                int p = ((nl >> 3) << 2) + (nl & 3);
                int slot = (nl >> 2) & 1;
                int idx = cc * 16 + ((p ^ sz) << 1) + slot;
                float val = vv[e];
                float h = tf32hi(val);
                aH[idx] = h;
                aL[idx] = val - h;
            }
        }
        {
            float vv[4] = { sr4.x, sr4.y, sr4.z, sr4.w };
            int sz = swz(crow);
#pragma unroll
            for (int e = 0; e < 4; ++e) {
                int nl = n4 + e;
                int p = ((nl >> 3) << 2) + (nl & 3);
                int slot = (nl >> 2) & 1;
                int idx = crow * 16 + ((p ^ sz) << 1) + slot;
                float val = vv[e];
                float h = tf32hi(val);
                bH[idx] = h;
                bL[idx] = val - h;
            }
        }
    };

    ldA(0); stA(0); ldA(1);
    __syncthreads();
    for (int ch = 0; ch < 32; ++ch) {
        if (ch + 1 < 32) stA((ch + 1) & 1);
        if (ch + 2 < 32) ldA(ch + 2);
        gemm_chunk(smem + (ch & 1) * BUF, c0w, g, q, acc);
        __syncthreads();
    }

    // epilogue: scatter D[c,k] partials
    float* basep = &g_wx8[seg][b][0][0];
#pragma unroll
    for (int i = 0; i < 2; ++i) {
        int cc = c0 + c0w + (i << 4) + g;
#pragma unroll
        for (int j = 0; j < 8; ++j) {
            int kc = (j << 3) + (q << 1);
            basep[(size_t)kc * Cq + cc]           = acc[i][j][0];
            basep[(size_t)(kc + 1) * Cq + cc]     = acc[i][j][1];
            basep[(size_t)kc * Cq + cc + 8]       = acc[i][j][2];
            basep[(size_t)(kc + 1) * Cq + cc + 8] = acc[i][j][3];
        }
    }
}

// ================= phase 3: nodes + per-row l2norm =================
__global__ void phase3_kernel(const float* __restrict__ anchor) {
    const int bk = blockIdx.x;     // 1024
    const int b = bk >> 6, k = bk & 63;
    const int tid = threadIdx.x;   // 128
    const float wsv = g_wsum[b][k];
    const float invw = 1.f / (wsv + 1e-9f);
    float t[4];
    float ssq = 0.f;
#pragma unroll
    for (int j = 0; j < 4; ++j) {
        int c = tid + j * 128;
        float wx = 0.f;
#pragma unroll
        for (int s = 0; s < 8; ++s) wx += g_wx8[s][b][k][c];
        float nd = (wx - wsv * anchor[k * Cq + c]) * gInvS[k][c] * invw;
        t[j] = nd;
        ssq += nd * nd;
    }
#pragma unroll
    for (int off = 16; off; off >>= 1) ssq += __shfl_xor_sync(0xffffffffu, ssq, off);
    __shared__ float red[4];
    __shared__ float totsh;
    if ((tid & 31) == 0) red[tid >> 5] = ssq;
    __syncthreads();
    if (tid == 0) totsh = red[0] + red[1] + red[2] + red[3];
    __syncthreads();
    float total = totsh;
    float scale = 1.f / fmaxf(sqrtf(total), 1e-12f);
#pragma unroll
    for (int j = 0; j < 4; ++j) {
        int c = tid + j * 128;
        g_nodes[b][k][c] = t[j] * scale;
    }
    if (tid == 0) g_row[b][k] = total * scale * scale;
}

// ================= phase 4: global l2norm + output =================
__global__ void phase4_kernel(float* __restrict__ outflat) {
    const int b = blockIdx.x;      // 16
    const int tid = threadIdx.x;   // 256
    __shared__ float red[64];
    __shared__ float gsh;
    if (tid < 64) red[tid] = g_row[b][tid];
    __syncthreads();
    if (tid == 0) {
        float s = 0.f;
#pragma unroll
        for (int i = 0; i < 64; ++i) s += red[i];
        gsh = 1.f / fmaxf(sqrtf(s), 1e-12f);
    }
    __syncthreads();
    float g = gsh;
    const float* np = &g_nodes[b][0][0];
    float* op = outflat + (size_t)b * Kq * Cq;
    for (int i = tid; i < Kq * Cq; i += 256) op[i] = np[i] * g;
}

// ================= launch =================
extern "C" void kernel_launch(void* const* d_in, const int* in_sizes, int n_in,
                              void* d_out, int out_size) {
    const float* x      = (const float*)d_in[0];
    const float* anchor = (const float*)d_in[1];
    const float* sraw   = (const float*)d_in[2];
    float* outf = (float*)d_out;

    const int FLAT = Bq * Cq * Kq;      // 524288
    const int SA   = Bq * Kq * Nq;      // 4194304

    float* sa_dev = nullptr;
    cudaGetSymbolAddress((void**)&sa_dev, g_sa);
    float* nodes_dev = nullptr;
    cudaGetSymbolAddress((void**)&nodes_dev, g_nodes);

    float* sa_ptr;
    float* flat_ptr;
    if (out_size == FLAT) {
        flat_ptr = outf;
        sa_ptr = sa_dev;
    } else if (out_size == SA) {
        sa_ptr = outf;
        flat_ptr = nodes_dev;
    } else {
        flat_ptr = outf;
        sa_ptr = outf + FLAT;
    }

    static bool attr_done = false;
    if (!attr_done) {
        cudaFuncSetAttribute(phase1_kernel,
                             cudaFuncAttributeMaxDynamicSharedMemorySize, P_SMEM);
        cudaFuncSetAttribute(phase2_kernel,
                             cudaFuncAttributeMaxDynamicSharedMemorySize, P_SMEM);
        attr_done = true;
    }

    prep_kernel<<<Kq, 256>>>(anchor, sraw);
    phase1_kernel<<<dim3(Nq / 256, Bq), 256, P_SMEM>>>(x, sa_ptr);
    wsum_kernel<<<Bq * Kq, 256>>>(sa_ptr);
    phase2_kernel<<<dim3(Cq / 256, Bq, 8), 256, P_SMEM>>>(x, sa_ptr);
    phase3_kernel<<<Bq * Kq, 128>>>(anchor);
    phase4_kernel<<<Bq, 256>>>(flat_ptr);
}

// round 8
// speedup vs baseline: 1.0991x; 1.0991x over previous
#include <cuda_runtime.h>
#include <cstdint>

#define Bq 16
#define Cq 512
#define Nq 4096
#define Kq 64

// ================= scratch (static device allocations only) =================
__device__ float4 gW4[64][512];       // per-chunk W images: [chunk][k*8+pp] = (W1h,W2h,W1l,W2l)
__device__ float gInvS[Kq][Cq];
__device__ float gCst[Kq];
__device__ float g_sa[(size_t)Bq*Kq*Nq];
__device__ float g_wx8[8][Bq][Kq][Cq];
__device__ float g_wsum[Bq][Kq];
__device__ float g_row[Bq][Kq];
__device__ float g_nodes[Bq][Kq][Cq];

// ================= helpers =================
__device__ __forceinline__ float tf32hi(float v) {
    return __uint_as_float(__float_as_uint(v) & 0xFFFFE000u);
}
// 3-bit swizzle keyed on row bits 0..2 (bit0 -> key bit2, bit1 -> key bit1, bit2 -> key bit0)
__device__ __forceinline__ int swz(int row) {
    return ((row & 1) << 2) | (((row >> 1) & 1) << 1) | ((row >> 2) & 1);
}
__device__ __forceinline__ void mma8(float* d, const unsigned* a, const unsigned* b) {
    asm volatile(
        "mma.sync.aligned.m16n8k8.row.col.f32.tf32.tf32.f32 "
        "{%0,%1,%2,%3}, {%4,%5,%6,%7}, {%8,%9}, {%0,%1,%2,%3};"
        : "+f"(d[0]), "+f"(d[1]), "+f"(d[2]), "+f"(d[3])
        : "r"(a[0]), "r"(a[1]), "r"(a[2]), "r"(a[3]), "r"(b[0]), "r"(b[1]));
}

// smem per buffer: A [256 rows][8 float4-slots] = 32KB, B [64][8 float4] = 8KB
#define OFF_A   0
#define OFF_B   32768
#define BUF     40960
#define P_SMEM  81920

// one 2-step chunk (16 reduction slots), warp tile 32(row) x 64(col), 3xTF32.
// Slot float4 = (hi_s0, hi_s1, lo_s0, lo_s1). Acc order hh->hl->lh per (s,j,i) as R6.
__device__ __forceinline__ void gemm_chunk(const char* bufp, int rowbase, int g, int q,
                                           float acc[2][8][4]) {
    const float4* fA = (const float4*)(bufp + OFF_A);
    const float4* fB = (const float4*)(bufp + OFF_B);
#pragma unroll
    for (int s = 0; s < 2; ++s) {
        const int p = (s << 2) + q;
        unsigned ah[2][4], al[2][4];
#pragma unroll
        for (int i = 0; i < 2; ++i) {
            int r0 = rowbase + (i << 4) + g;
            int r1 = r0 + 8;
            float4 f0 = fA[r0 * 8 + (p ^ swz(r0))];
            float4 f1 = fA[r1 * 8 + (p ^ swz(r1))];
            ah[i][0] = __float_as_uint(f0.x); ah[i][2] = __float_as_uint(f0.y);
            al[i][0] = __float_as_uint(f0.z); al[i][2] = __float_as_uint(f0.w);
            ah[i][1] = __float_as_uint(f1.x); ah[i][3] = __float_as_uint(f1.y);
            al[i][1] = __float_as_uint(f1.z); al[i][3] = __float_as_uint(f1.w);
        }
#pragma unroll
        for (int j = 0; j < 8; ++j) {
            int k = (j << 3) + g;
            float4 fb = fB[k * 8 + (p ^ swz(k))];
            unsigned bh[2] = { __float_as_uint(fb.x), __float_as_uint(fb.y) };
            unsigned bl[2] = { __float_as_uint(fb.z), __float_as_uint(fb.w) };
#pragma unroll
            for (int i = 0; i < 2; ++i) {
                mma8(acc[i][j], ah[i], bh);
                mma8(acc[i][j], ah[i], bl);
                mma8(acc[i][j], al[i], bh);
            }
        }
    }
}

// ================= prep: sigma, W images, const =================
__global__ void prep_kernel(const float* __restrict__ anchor,
                            const float* __restrict__ sraw) {
    const int k = blockIdx.x;       // 64
    const int tid = threadIdx.x;    // 256
    float part = 0.f;
#pragma unroll
    for (int j = 0; j < 2; ++j) {
        int c = tid + j * 256;
        float sr = sraw[k * Cq + c];
        float sg = 1.f / (1.f + __expf(-sr));
        float a  = anchor[k * Cq + c];
        float i2 = 1.f / (sg * sg);
        float w2 = -2.f * a * i2;
        gInvS[k][c] = 1.f / sg;
        part += a * a * i2;
        int ch = c >> 3, p = c & 7;
        int pp = p ^ swz(k);
        float i2h = tf32hi(i2), w2h = tf32hi(w2);
        gW4[ch][k * 8 + pp] = make_float4(i2h, w2h, i2 - i2h, w2 - w2h);
    }
#pragma unroll
    for (int off = 16; off; off >>= 1) part += __shfl_xor_sync(0xffffffffu, part, off);
    __shared__ float red[8];
    if ((tid & 31) == 0) red[tid >> 5] = part;
    __syncthreads();
    if (tid == 0) {
        float s = 0.f;
#pragma unroll
        for (int i = 0; i < 8; ++i) s += red[i];
        gCst[k] = s;
    }
}

// ================= phase 1: distance GEMM (3xTF32 mma) + softmax =================
// block = (n-tile 256, b). warp tile 32n x 64k. 64 chunks of 8 c (16 c2 slots).
__global__ __launch_bounds__(256, 2)
void phase1_kernel(const float* __restrict__ x, float* __restrict__ sa) {
    extern __shared__ char smem[];
    __shared__ float cst[64];
    const int tid = threadIdx.x;
    const int w = tid >> 5, lane = tid & 31;
    const int g = lane >> 2, q = lane & 3;
    const int n0w = w << 5;
    const int b  = blockIdx.y;
    const int n0 = blockIdx.x << 8;
    const float* xb = x + (size_t)b * Cq * Nq + n0;
    if (tid < 64) cst[tid] = gCst[tid];

    float acc[2][8][4];
#pragma unroll
    for (int i = 0; i < 2; ++i)
#pragma unroll
        for (int j = 0; j < 8; ++j)
#pragma unroll
            for (int e = 0; e < 4; ++e) acc[i][j][e] = 0.f;

    const int sz_n = swz(tid);
    auto fill = [&](int ch, int buf) {
        char* bp = smem + buf * BUF;
        // W image copy: 512 float4 / 256 threads
        ((float4*)(bp + OFF_B))[tid]       = ((const float4*)&gW4[ch][0])[tid];
        ((float4*)(bp + OFF_B))[tid + 256] = ((const float4*)&gW4[ch][0])[tid + 256];
        // A build: thread owns row n = tid, 8 c-slots
        float4* fA = (float4*)(bp + OFF_A);
        const float* xp = xb + (size_t)(ch << 3) * Nq + tid;
#pragma unroll
        for (int cl = 0; cl < 8; ++cl) {
            float v = xp[(size_t)cl * Nq];
            float v2 = v * v;
            float vh = tf32hi(v),  vl = v - vh;
            float qh = tf32hi(v2), ql = v2 - qh;
            fA[tid * 8 + (cl ^ sz_n)] = make_float4(qh, vh, ql, vl); // s0=x^2, s1=x
        }
    };

    fill(0, 0);
    __syncthreads();
    for (int ch = 0; ; ++ch) {
        if (ch + 1 < 64) fill(ch + 1, (ch + 1) & 1);
        gemm_chunk(smem + (ch & 1) * BUF, n0w, g, q, acc);
        if (ch + 1 == 64) break;
        __syncthreads();
    }
    __syncthreads();

    // stage d2 in smem (overlays buffers)
    float* d2 = (float*)smem;
#pragma unroll
    for (int i = 0; i < 2; ++i) {
        int r0 = n0w + (i << 4) + g;
#pragma unroll
        for (int j = 0; j < 8; ++j) {
            int kc = (j << 3) + (q << 1);
            *(float2*)&d2[r0 * 66 + kc]       = make_float2(acc[i][j][0], acc[i][j][1]);
            *(float2*)&d2[(r0 + 8) * 66 + kc] = make_float2(acc[i][j][2], acc[i][j][3]);
        }
    }
    __syncthreads();

    // softmax: one thread per n
    {
        float e[64];
#pragma unroll
        for (int k = 0; k < 64; ++k) e[k] = d2[tid * 66 + k] + cst[k];
        float mn = e[0];
#pragma unroll
        for (int k = 1; k < 64; ++k) mn = fminf(mn, e[k]);
        float s = 0.f;
#pragma unroll
        for (int k = 0; k < 64; ++k) {
            float t = __expf(-0.5f * (e[k] - mn));
            e[k] = t;
            s += t;
        }
        float r = 1.f / s;
        float* sp = sa + (size_t)b * Kq * Nq + n0 + tid;
#pragma unroll
        for (int k = 0; k < 64; ++k) sp[(size_t)k * Nq] = e[k] * r;
    }
}

// ================= w_sum =================
__global__ void wsum_kernel(const float* __restrict__ sa) {
    const int bk = blockIdx.x;      // 1024
    const int tid = threadIdx.x;    // 256
    const float4* row = reinterpret_cast<const float4*>(sa + (size_t)bk * Nq);
    float s = 0.f;
#pragma unroll
    for (int i = 0; i < 4; ++i) {
        float4 v = row[tid + i * 256];
        s += (v.x + v.y) + (v.z + v.w);
    }
#pragma unroll
    for (int off = 16; off; off >>= 1) s += __shfl_xor_sync(0xffffffffu, s, off);
    __shared__ float red[8];
    if ((tid & 31) == 0) red[tid >> 5] = s;
    __syncthreads();
    if (tid == 0) {
        float t = 0.f;
#pragma unroll
        for (int i = 0; i < 8; ++i) t += red[i];
        g_wsum[bk >> 6][bk & 63] = t;
    }
}

// ================= phase 2: wx[c,k] = sum_n x[c,n]*sa[k,n] (3xTF32 mma) =================
// grid (2 ctile, 16 b, 8 seg). block tile 256c x 64k, 32 chunks of 16 n.
__global__ __launch_bounds__(256, 2)
void phase2_kernel(const float* __restrict__ x, const float* __restrict__ sa) {
    extern __shared__ char smem[];
    const int tid = threadIdx.x;
    const int w = tid >> 5, lane = tid & 31;
    const int g = lane >> 2, q = lane & 3;
    const int c0w = w << 5;
    const int c0 = (int)blockIdx.x << 8;
    const int b  = blockIdx.y;
    const int seg = blockIdx.z;
    const int n0 = seg << 9;
    const float* xb = x  + ((size_t)b * Cq + c0) * Nq + n0;
    const float* sb = sa + (size_t)b * Kq * Nq + n0;

    float acc[2][8][4];
#pragma unroll
    for (int i = 0; i < 2; ++i)
#pragma unroll
        for (int j = 0; j < 8; ++j)
#pragma unroll
            for (int e = 0; e < 4; ++e) acc[i][j][e] = 0.f;

    // fill: unit = (row, half-of-16n). slot p holds (hi@nl=p_s0, hi@nl+4_s1, lo, lo).
    auto fill = [&](int ch, int buf) {
        char* bp = smem + buf * BUF;
        float4* fA = (float4*)(bp + OFF_A);
        float4* fB = (float4*)(bp + OFF_B);
        const int nn = ch << 4;
#pragma unroll
        for (int uu = 0; uu < 2; ++uu) {
            int u = tid + (uu << 8);
            int row = u >> 1, half = u & 1;
            const float* src = xb + (size_t)row * Nq + nn + (half << 3);
            float4 v0 = *(const float4*)(src);
            float4 v1 = *(const float4*)(src + 4);
            int sz = swz(row);
            float a0[4] = { v0.x, v0.y, v0.z, v0.w };   // s0 values
            float a1[4] = { v1.x, v1.y, v1.z, v1.w };   // s1 values
#pragma unroll
            for (int t = 0; t < 4; ++t) {
                int p = (half << 2) + t;
                float h0 = tf32hi(a0[t]), l0 = a0[t] - h0;
                float h1 = tf32hi(a1[t]), l1 = a1[t] - h1;
                fA[row * 8 + (p ^ sz)] = make_float4(h0, h1, l0, l1);
            }
        }
        if (tid < 128) {
            int row = tid >> 1, half = tid & 1;
            const float* src = sb + (size_t)row * Nq + nn + (half << 3);
            float4 v0 = *(const float4*)(src);
            float4 v1 = *(const float4*)(src + 4);
            int sz = swz(row);
            float a0[4] = { v0.x, v0.y, v0.z, v0.w };
            float a1[4] = { v1.x, v1.y, v1.z, v1.w };
#pragma unroll
            for (int t = 0; t < 4; ++t) {
                int p = (half << 2) + t;
                float h0 = tf32hi(a0[t]), l0 = a0[t] - h0;
                float h1 = tf32hi(a1[t]), l1 = a1[t] - h1;
                fB[row * 8 + (p ^ sz)] = make_float4(h0, h1, l0, l1);
            }
        }
    };

    fill(0, 0);
    __syncthreads();
    for (int ch = 0; ; ++ch) {
        if (ch + 1 < 32) fill(ch + 1, (ch + 1) & 1);
        gemm_chunk(smem + (ch & 1) * BUF, c0w, g, q, acc);
        if (ch + 1 == 32) break;
        __syncthreads();
    }

    // epilogue: scatter D[c,k] partials
    float* basep = &g_wx8[seg][b][0][0];
#pragma unroll
    for (int i = 0; i < 2; ++i) {
        int cc = c0 + c0w + (i << 4) + g;
#pragma unroll
        for (int j = 0; j < 8; ++j) {
            int kc = (j << 3) + (q << 1);
            basep[(size_t)kc * Cq + cc]           = acc[i][j][0];
            basep[(size_t)(kc + 1) * Cq + cc]     = acc[i][j][1];
            basep[(size_t)kc * Cq + cc + 8]       = acc[i][j][2];
            basep[(size_t)(kc + 1) * Cq + cc + 8] = acc[i][j][3];
        }
    }
}

// ================= phase 3: nodes + per-row l2norm =================
__global__ void phase3_kernel(const float* __restrict__ anchor) {
    const int bk = blockIdx.x;     // 1024
    const int b = bk >> 6, k = bk & 63;
    const int tid = threadIdx.x;   // 128
    const float wsv = g_wsum[b][k];
    const float invw = 1.f / (wsv + 1e-9f);
    float t[4];
    float ssq = 0.f;
#pragma unroll
    for (int j = 0; j < 4; ++j) {
        int c = tid + j * 128;
        float wx = 0.f;
#pragma unroll
        for (int s = 0; s < 8; ++s) wx += g_wx8[s][b][k][c];
        float nd = (wx - wsv * anchor[k * Cq + c]) * gInvS[k][c] * invw;
        t[j] = nd;
        ssq += nd * nd;
    }
#pragma unroll
    for (int off = 16; off; off >>= 1) ssq += __shfl_xor_sync(0xffffffffu, ssq, off);
    __shared__ float red[4];
    __shared__ float totsh;
    if ((tid & 31) == 0) red[tid >> 5] = ssq;
    __syncthreads();
    if (tid == 0) totsh = red[0] + red[1] + red[2] + red[3];
    __syncthreads();
    float total = totsh;
    float scale = 1.f / fmaxf(sqrtf(total), 1e-12f);
#pragma unroll
    for (int j = 0; j < 4; ++j) {
        int c = tid + j * 128;
        g_nodes[b][k][c] = t[j] * scale;
    }
    if (tid == 0) g_row[b][k] = total * scale * scale;
}

// ================= phase 4: global l2norm + output =================
__global__ void phase4_kernel(float* __restrict__ outflat) {
    const int b = blockIdx.x;      // 16
    const int tid = threadIdx.x;   // 256
    __shared__ float red[64];
    __shared__ float gsh;
    if (tid < 64) red[tid] = g_row[b][tid];
    __syncthreads();
    if (tid == 0) {
        float s = 0.f;
#pragma unroll
        for (int i = 0; i < 64; ++i) s += red[i];
        gsh = 1.f / fmaxf(sqrtf(s), 1e-12f);
    }
    __syncthreads();
    float g = gsh;
    const float* np = &g_nodes[b][0][0];
    float* op = outflat + (size_t)b * Kq * Cq;
    for (int i = tid; i < Kq * Cq; i += 256) op[i] = np[i] * g;
}

// ================= launch =================
extern "C" void kernel_launch(void* const* d_in, const int* in_sizes, int n_in,
                              void* d_out, int out_size) {
    const float* x      = (const float*)d_in[0];
    const float* anchor = (const float*)d_in[1];
    const float* sraw   = (const float*)d_in[2];
    float* outf = (float*)d_out;

    const int FLAT = Bq * Cq * Kq;      // 524288
    const int SA   = Bq * Kq * Nq;      // 4194304

    float* sa_dev = nullptr;
    cudaGetSymbolAddress((void**)&sa_dev, g_sa);
    float* nodes_dev = nullptr;
    cudaGetSymbolAddress((void**)&nodes_dev, g_nodes);

    float* sa_ptr;
    float* flat_ptr;
    if (out_size == FLAT) {
        flat_ptr = outf;
        sa_ptr = sa_dev;
    } else if (out_size == SA) {
        sa_ptr = outf;
        flat_ptr = nodes_dev;
    } else {
        flat_ptr = outf;
        sa_ptr = outf + FLAT;
    }

    static bool attr_done = false;
    if (!attr_done) {
        cudaFuncSetAttribute(phase1_kernel,
                             cudaFuncAttributeMaxDynamicSharedMemorySize, P_SMEM);
        cudaFuncSetAttribute(phase2_kernel,
                             cudaFuncAttributeMaxDynamicSharedMemorySize, P_SMEM);
        attr_done = true;
    }

    prep_kernel<<<Kq, 256>>>(anchor, sraw);
    phase1_kernel<<<dim3(Nq / 256, Bq), 256, P_SMEM>>>(x, sa_ptr);
    wsum_kernel<<<Bq * Kq, 256>>>(sa_ptr);
    phase2_kernel<<<dim3(Cq / 256, Bq, 8), 256, P_SMEM>>>(x, sa_ptr);
    phase3_kernel<<<Bq * Kq, 128>>>(anchor);
    phase4_kernel<<<Bq, 256>>>(flat_ptr);
}

// round 9
// speedup vs baseline: 1.5865x; 1.4435x over previous
#include <cuda_runtime.h>
#include <cstdint>

#define Bq 16
#define Cq 512
#define Nq 4096
#define Kq 64

// ================= scratch (static device allocations only) =================
__device__ float4 gW4[64][512];       // per-8c-chunk W images: [chunk][k*8+pp] = (W1h,W2h,W1l,W2l)
__device__ float gInvS[Kq][Cq];
__device__ float gCst[Kq];
__device__ float g_sa[(size_t)Bq*Kq*Nq];
__device__ float g_wx8[8][Bq][Kq][Cq];
__device__ float g_wsum[Bq][Kq];
__device__ float g_row[Bq][Kq];
__device__ float g_nodes[Bq][Kq][Cq];

// ================= helpers =================
__device__ __forceinline__ float tf32hi(float v) {
    return __uint_as_float(__float_as_uint(v) & 0xFFFFE000u);
}
// 3-bit swizzle keyed on row bits 0..2
__device__ __forceinline__ int swz(int row) {
    return ((row & 1) << 2) | (((row >> 1) & 1) << 1) | ((row >> 2) & 1);
}
__device__ __forceinline__ void mma8(float* d, const unsigned* a, const unsigned* b) {
    asm volatile(
        "mma.sync.aligned.m16n8k8.row.col.f32.tf32.tf32.f32 "
        "{%0,%1,%2,%3}, {%4,%5,%6,%7}, {%8,%9}, {%0,%1,%2,%3};"
        : "+f"(d[0]), "+f"(d[1]), "+f"(d[2]), "+f"(d[3])
        : "r"(a[0]), "r"(a[1]), "r"(a[2]), "r"(a[3]), "r"(b[0]), "r"(b[1]));
}
__device__ __forceinline__ uint32_t smem_u32(const void* p) {
    uint32_t a;
    asm("{ .reg .u64 t; cvta.to.shared.u64 t, %1; cvt.u32.u64 %0, t; }" : "=r"(a) : "l"(p));
    return a;
}
#define CP16(dst, src) asm volatile("cp.async.cg.shared.global [%0], [%1], 16;" :: "r"(dst), "l"(src))
#define CPCOMMIT()     asm volatile("cp.async.commit_group;" ::: "memory")
#define CPWAIT1()      asm volatile("cp.async.wait_group 1;" ::: "memory")
#define CPWAIT0()      asm volatile("cp.async.wait_group 0;" ::: "memory")

// ===== phase1 smem: A raw x [16c][264f] (256 used), B = 2 W sub-images =====
#define P1_OFFA(b) ((b) * 16896u)
#define P1_OFFB(b) (33792u + (b) * 16384u)
#define P1_SMEM 69632
// ===== phase2 smem: A raw x [256c][36f] (32 used), B raw sa [64k][36f] =====
#define P2_OFFA(b) ((b) * 36864u)
#define P2_OFFB(b) (73728u + (b) * 9216u)
#define P2_SMEM 92160

// ================= prep: sigma, W images, const =================
__global__ void prep_kernel(const float* __restrict__ anchor,
                            const float* __restrict__ sraw) {
    const int k = blockIdx.x;       // 64
    const int tid = threadIdx.x;    // 256
    float part = 0.f;
#pragma unroll
    for (int j = 0; j < 2; ++j) {
        int c = tid + j * 256;
        float sr = sraw[k * Cq + c];
        float sg = 1.f / (1.f + __expf(-sr));
        float a  = anchor[k * Cq + c];
        float i2 = 1.f / (sg * sg);
        float w2 = -2.f * a * i2;
        gInvS[k][c] = 1.f / sg;
        part += a * a * i2;
        int ch = c >> 3, p = c & 7;
        int pp = p ^ swz(k);
        float i2h = tf32hi(i2), w2h = tf32hi(w2);
        gW4[ch][k * 8 + pp] = make_float4(i2h, w2h, i2 - i2h, w2 - w2h);
    }
#pragma unroll
    for (int off = 16; off; off >>= 1) part += __shfl_xor_sync(0xffffffffu, part, off);
    __shared__ float red[8];
    if ((tid & 31) == 0) red[tid >> 5] = part;
    __syncthreads();
    if (tid == 0) {
        float s = 0.f;
#pragma unroll
        for (int i = 0; i < 8; ++i) s += red[i];
        gCst[k] = s;
    }
}

// ================= phase 1: distance GEMM (3xTF32 mma) + softmax =================
// block = (n-tile 256, b). warp tile 32n x 64k. 32 chunks of 16 c (4 mma steps each).
__global__ __launch_bounds__(256, 2)
void phase1_kernel(const float* __restrict__ x, float* __restrict__ sa) {
    extern __shared__ char smem[];
    __shared__ float cst[64];
    const uint32_t sb = smem_u32(smem);
    const int tid = threadIdx.x;
    const int w = tid >> 5, lane = tid & 31;
    const int g = lane >> 2, q = lane & 3;
    const int n0w = w << 5;
    const int b  = blockIdx.y;
    const int n0 = blockIdx.x << 8;
    const float* xb = x + (size_t)b * Cq * Nq + n0;
    if (tid < 64) cst[tid] = gCst[tid];

    float acc[2][8][4];
#pragma unroll
    for (int i = 0; i < 2; ++i)
#pragma unroll
        for (int j = 0; j < 8; ++j)
#pragma unroll
            for (int e = 0; e < 4; ++e) acc[i][j][e] = 0.f;

    auto fill = [&](int ch) {
        const int buf = ch & 1;
        const float* xc = xb + (size_t)(ch << 4) * Nq;
        // A: 16 rows(c) x 256n -> 1024 x 16B
#pragma unroll
        for (int it = 0; it < 4; ++it) {
            int u = tid + (it << 8);
            int row = u >> 6, seg = u & 63;
            uint32_t dst = sb + P1_OFFA(buf) + (uint32_t)row * 1056u + (uint32_t)(seg << 4);
            CP16(dst, xc + (size_t)row * Nq + (seg << 2));
        }
        // B: two W sub-images, contiguous 1024 float4
        const float4* wsrc = &gW4[ch << 1][0];
#pragma unroll
        for (int it = 0; it < 4; ++it) {
            int u = tid + (it << 8);
            uint32_t dst = sb + P1_OFFB(buf) + (uint32_t)(u << 4);
            CP16(dst, wsrc + u);
        }
        CPCOMMIT();
    };

    auto gemm = [&](int buf) {
        const float* fA = (const float*)(smem + P1_OFFA(buf));
        const float4* fB = (const float4*)(smem + P1_OFFB(buf));
#pragma unroll
        for (int s = 0; s < 4; ++s) {
            const int crow = (s << 2) + q;
            const float* arow = fA + crow * 264 + n0w + g;
            float v0 = arow[0], v1 = arow[8], v2 = arow[16], v3 = arow[24];
            unsigned ah[2][4], al[2][4];
            {
                float q0 = v0 * v0, q1 = v1 * v1, h;
                h = tf32hi(q0); ah[0][0] = __float_as_uint(h); al[0][0] = __float_as_uint(q0 - h);
                h = tf32hi(q1); ah[0][1] = __float_as_uint(h); al[0][1] = __float_as_uint(q1 - h);
                h = tf32hi(v0); ah[0][2] = __float_as_uint(h); al[0][2] = __float_as_uint(v0 - h);
                h = tf32hi(v1); ah[0][3] = __float_as_uint(h); al[0][3] = __float_as_uint(v1 - h);
                float q2 = v2 * v2, q3 = v3 * v3;
                h = tf32hi(q2); ah[1][0] = __float_as_uint(h); al[1][0] = __float_as_uint(q2 - h);
                h = tf32hi(q3); ah[1][1] = __float_as_uint(h); al[1][1] = __float_as_uint(q3 - h);
                h = tf32hi(v2); ah[1][2] = __float_as_uint(h); al[1][2] = __float_as_uint(v2 - h);
                h = tf32hi(v3); ah[1][3] = __float_as_uint(h); al[1][3] = __float_as_uint(v3 - h);
            }
            const float4* fBs = fB + (s >> 1) * 512;
            const int pl = ((s & 1) << 2) + q;
#pragma unroll
            for (int jh = 0; jh < 2; ++jh) {
                float4 fb[4];
#pragma unroll
                for (int jj = 0; jj < 4; ++jj) {
                    int k = (((jh << 2) + jj) << 3) + g;
                    fb[jj] = fBs[k * 8 + (pl ^ swz(k))];
                }
                // hh pass
#pragma unroll
                for (int jj = 0; jj < 4; ++jj) {
                    unsigned bh[2] = { __float_as_uint(fb[jj].x), __float_as_uint(fb[jj].y) };
                    mma8(acc[0][(jh << 2) + jj], ah[0], bh);
                    mma8(acc[1][(jh << 2) + jj], ah[1], bh);
                }
                // hl pass
#pragma unroll
                for (int jj = 0; jj < 4; ++jj) {
                    unsigned bl[2] = { __float_as_uint(fb[jj].z), __float_as_uint(fb[jj].w) };
                    mma8(acc[0][(jh << 2) + jj], ah[0], bl);
                    mma8(acc[1][(jh << 2) + jj], ah[1], bl);
                }
                // lh pass
#pragma unroll
                for (int jj = 0; jj < 4; ++jj) {
                    unsigned bh[2] = { __float_as_uint(fb[jj].x), __float_as_uint(fb[jj].y) };
                    mma8(acc[0][(jh << 2) + jj], al[0], bh);
                    mma8(acc[1][(jh << 2) + jj], al[1], bh);
                }
            }
        }
    };

    fill(0); fill(1);
    for (int ch = 0; ch < 32; ++ch) {
        if (ch + 1 < 32) { CPWAIT1(); } else { CPWAIT0(); }
        __syncthreads();
        gemm(ch & 1);
        __syncthreads();
        if (ch + 2 < 32) fill(ch + 2);
    }

    // stage d2 in smem (overlays buffers; all cp.async drained above)
    float* d2 = (float*)smem;
#pragma unroll
    for (int i = 0; i < 2; ++i) {
        int r0 = n0w + (i << 4) + g;
#pragma unroll
        for (int j = 0; j < 8; ++j) {
            int kc = (j << 3) + (q << 1);
            *(float2*)&d2[r0 * 66 + kc]       = make_float2(acc[i][j][0], acc[i][j][1]);
            *(float2*)&d2[(r0 + 8) * 66 + kc] = make_float2(acc[i][j][2], acc[i][j][3]);
        }
    }
    __syncthreads();

    // softmax: one thread per n
    {
        float e[64];
#pragma unroll
        for (int k = 0; k < 64; ++k) e[k] = d2[tid * 66 + k] + cst[k];
        float mn = e[0];
#pragma unroll
        for (int k = 1; k < 64; ++k) mn = fminf(mn, e[k]);
        float s = 0.f;
#pragma unroll
        for (int k = 0; k < 64; ++k) {
            float t = __expf(-0.5f * (e[k] - mn));
            e[k] = t;
            s += t;
        }
        float r = 1.f / s;
        float* sp = sa + (size_t)b * Kq * Nq + n0 + tid;
#pragma unroll
        for (int k = 0; k < 64; ++k) sp[(size_t)k * Nq] = e[k] * r;
    }
}

// ================= w_sum =================
__global__ void wsum_kernel(const float* __restrict__ sa) {
    const int bk = blockIdx.x;      // 1024
    const int tid = threadIdx.x;    // 256
    const float4* row = reinterpret_cast<const float4*>(sa + (size_t)bk * Nq);
    float s = 0.f;
#pragma unroll
    for (int i = 0; i < 4; ++i) {
        float4 v = row[tid + i * 256];
        s += (v.x + v.y) + (v.z + v.w);
    }
#pragma unroll
    for (int off = 16; off; off >>= 1) s += __shfl_xor_sync(0xffffffffu, s, off);
    __shared__ float red[8];
    if ((tid & 31) == 0) red[tid >> 5] = s;
    __syncthreads();
    if (tid == 0) {
        float t = 0.f;
#pragma unroll
        for (int i = 0; i < 8; ++i) t += red[i];
        g_wsum[bk >> 6][bk & 63] = t;
    }
}

// ================= phase 2: wx[c,k] = sum_n x[c,n]*sa[k,n] (3xTF32 mma) =================
// grid (2 ctile, 16 b, 8 seg). block tile 256c x 64k, 16 chunks of 32 n (4 steps).
__global__ __launch_bounds__(256, 2)
void phase2_kernel(const float* __restrict__ x, const float* __restrict__ sa) {
    extern __shared__ char smem[];
    const uint32_t sb = smem_u32(smem);
    const int tid = threadIdx.x;
    const int w = tid >> 5, lane = tid & 31;
    const int g = lane >> 2, q = lane & 3;
    const int c0w = w << 5;
    const int c0 = (int)blockIdx.x << 8;
    const int b  = blockIdx.y;
    const int seg = blockIdx.z;
    const int n0 = seg << 9;
    const float* xb = x  + ((size_t)b * Cq + c0) * Nq + n0;
    const float* sbp = sa + (size_t)b * Kq * Nq + n0;

    float acc[2][8][4];
#pragma unroll
    for (int i = 0; i < 2; ++i)
#pragma unroll
        for (int j = 0; j < 8; ++j)
#pragma unroll
            for (int e = 0; e < 4; ++e) acc[i][j][e] = 0.f;

    auto fill = [&](int ch) {
        const int buf = ch & 1;
        const int nn = ch << 5;
        // A: 256 rows(c) x 32n -> 2048 x 16B
#pragma unroll
        for (int it = 0; it < 8; ++it) {
            int u = tid + (it << 8);
            int row = u >> 3, sg2 = u & 7;
            uint32_t dst = sb + P2_OFFA(buf) + (uint32_t)row * 144u + (uint32_t)(sg2 << 4);
            CP16(dst, xb + (size_t)row * Nq + nn + (sg2 << 2));
        }
        // B: 64 rows(k) x 32n -> 512 x 16B
#pragma unroll
        for (int it = 0; it < 2; ++it) {
            int u = tid + (it << 8);
            int row = u >> 3, sg2 = u & 7;
            uint32_t dst = sb + P2_OFFB(buf) + (uint32_t)row * 144u + (uint32_t)(sg2 << 4);
            CP16(dst, sbp + (size_t)row * Nq + nn + (sg2 << 2));
        }
        CPCOMMIT();
    };

    auto gemm = [&](int buf) {
        const float* fA = (const float*)(smem + P2_OFFA(buf));
        const float* fB = (const float*)(smem + P2_OFFB(buf));
#pragma unroll
        for (int s = 0; s < 4; ++s) {
            const int nb8 = s << 3;
            unsigned ah[2][4], al[2][4];
#pragma unroll
            for (int i = 0; i < 2; ++i) {
                int r0 = c0w + (i << 4) + g;
                float x0 = fA[r0 * 36 + nb8 + q];
                float x1 = fA[(r0 + 8) * 36 + nb8 + q];
                float x2 = fA[r0 * 36 + nb8 + q + 4];
                float x3 = fA[(r0 + 8) * 36 + nb8 + q + 4];
                float h;
                h = tf32hi(x0); ah[i][0] = __float_as_uint(h); al[i][0] = __float_as_uint(x0 - h);
                h = tf32hi(x1); ah[i][1] = __float_as_uint(h); al[i][1] = __float_as_uint(x1 - h);
                h = tf32hi(x2); ah[i][2] = __float_as_uint(h); al[i][2] = __float_as_uint(x2 - h);
                h = tf32hi(x3); ah[i][3] = __float_as_uint(h); al[i][3] = __float_as_uint(x3 - h);
            }
#pragma unroll
            for (int jh = 0; jh < 2; ++jh) {
                unsigned bh[4][2], bl[4][2];
#pragma unroll
                for (int jj = 0; jj < 4; ++jj) {
                    int k = (((jh << 2) + jj) << 3) + g;
                    float y0 = fB[k * 36 + nb8 + q];
                    float y1 = fB[k * 36 + nb8 + q + 4];
                    float h;
                    h = tf32hi(y0); bh[jj][0] = __float_as_uint(h); bl[jj][0] = __float_as_uint(y0 - h);
                    h = tf32hi(y1); bh[jj][1] = __float_as_uint(h); bl[jj][1] = __float_as_uint(y1 - h);
                }
#pragma unroll
                for (int jj = 0; jj < 4; ++jj) {
                    mma8(acc[0][(jh << 2) + jj], ah[0], bh[jj]);
                    mma8(acc[1][(jh << 2) + jj], ah[1], bh[jj]);
                }
#pragma unroll
                for (int jj = 0; jj < 4; ++jj) {
                    mma8(acc[0][(jh << 2) + jj], ah[0], bl[jj]);
                    mma8(acc[1][(jh << 2) + jj], ah[1], bl[jj]);
                }
#pragma unroll
                for (int jj = 0; jj < 4; ++jj) {
                    mma8(acc[0][(jh << 2) + jj], al[0], bh[jj]);
                    mma8(acc[1][(jh << 2) + jj], al[1], bh[jj]);
                }
            }
        }
    };

    fill(0); fill(1);
    for (int ch = 0; ch < 16; ++ch) {
        if (ch + 1 < 16) { CPWAIT1(); } else { CPWAIT0(); }
        __syncthreads();
        gemm(ch & 1);
        __syncthreads();
        if (ch + 2 < 16) fill(ch + 2);
    }

    // epilogue: scatter D[c,k] partials
    float* basep = &g_wx8[seg][b][0][0];
#pragma unroll
    for (int i = 0; i < 2; ++i) {
        int cc = c0 + c0w + (i << 4) + g;
#pragma unroll
        for (int j = 0; j < 8; ++j) {
            int kc = (j << 3) + (q << 1);
            basep[(size_t)kc * Cq + cc]           = acc[i][j][0];
            basep[(size_t)(kc + 1) * Cq + cc]     = acc[i][j][1];
            basep[(size_t)kc * Cq + cc + 8]       = acc[i][j][2];
            basep[(size_t)(kc + 1) * Cq + cc + 8] = acc[i][j][3];
        }
    }
}

// ================= phase 3: nodes + per-row l2norm =================
__global__ void phase3_kernel(const float* __restrict__ anchor) {
    const int bk = blockIdx.x;     // 1024
    const int b = bk >> 6, k = bk & 63;
    const int tid = threadIdx.x;   // 128
    const float wsv = g_wsum[b][k];
    const float invw = 1.f / (wsv + 1e-9f);
    float t[4];
    float ssq = 0.f;
#pragma unroll
    for (int j = 0; j < 4; ++j) {
        int c = tid + j * 128;
        float wx = 0.f;
#pragma unroll
        for (int s = 0; s < 8; ++s) wx += g_wx8[s][b][k][c];
        float nd = (wx - wsv * anchor[k * Cq + c]) * gInvS[k][c] * invw;
        t[j] = nd;
        ssq += nd * nd;
    }
#pragma unroll
    for (int off = 16; off; off >>= 1) ssq += __shfl_xor_sync(0xffffffffu, ssq, off);
    __shared__ float red[4];
    __shared__ float totsh;
    if ((tid & 31) == 0) red[tid >> 5] = ssq;
    __syncthreads();
    if (tid == 0) totsh = red[0] + red[1] + red[2] + red[3];
    __syncthreads();
    float total = totsh;
    float scale = 1.f / fmaxf(sqrtf(total), 1e-12f);
#pragma unroll
    for (int j = 0; j < 4; ++j) {
        int c = tid + j * 128;
        g_nodes[b][k][c] = t[j] * scale;
    }
    if (tid == 0) g_row[b][k] = total * scale * scale;
}

// ================= phase 4: global l2norm + output =================
__global__ void phase4_kernel(float* __restrict__ outflat) {
    const int b = blockIdx.x;      // 16
    const int tid = threadIdx.x;   // 256
    __shared__ float red[64];
    __shared__ float gsh;
    if (tid < 64) red[tid] = g_row[b][tid];
    __syncthreads();
    if (tid == 0) {
        float s = 0.f;
#pragma unroll
        for (int i = 0; i < 64; ++i) s += red[i];
        gsh = 1.f / fmaxf(sqrtf(s), 1e-12f);
    }
    __syncthreads();
    float g = gsh;
    const float* np = &g_nodes[b][0][0];
    float* op = outflat + (size_t)b * Kq * Cq;
    for (int i = tid; i < Kq * Cq; i += 256) op[i] = np[i] * g;
}

// ================= launch =================
extern "C" void kernel_launch(void* const* d_in, const int* in_sizes, int n_in,
                              void* d_out, int out_size) {
    const float* x      = (const float*)d_in[0];
    const float* anchor = (const float*)d_in[1];
    const float* sraw   = (const float*)d_in[2];
    float* outf = (float*)d_out;

    const int FLAT = Bq * Cq * Kq;      // 524288
    const int SA   = Bq * Kq * Nq;      // 4194304

    float* sa_dev = nullptr;
    cudaGetSymbolAddress((void**)&sa_dev, g_sa);
    float* nodes_dev = nullptr;
    cudaGetSymbolAddress((void**)&nodes_dev, g_nodes);

    float* sa_ptr;
    float* flat_ptr;
    if (out_size == FLAT) {
        flat_ptr = outf;
        sa_ptr = sa_dev;
    } else if (out_size == SA) {
        sa_ptr = outf;
        flat_ptr = nodes_dev;
    } else {
        flat_ptr = outf;
        sa_ptr = outf + FLAT;
    }

    static bool attr_done = false;
    if (!attr_done) {
        cudaFuncSetAttribute(phase1_kernel,
                             cudaFuncAttributeMaxDynamicSharedMemorySize, P1_SMEM);
        cudaFuncSetAttribute(phase2_kernel,
                             cudaFuncAttributeMaxDynamicSharedMemorySize, P2_SMEM);
        attr_done = true;
    }

    prep_kernel<<<Kq, 256>>>(anchor, sraw);
    phase1_kernel<<<dim3(Nq / 256, Bq), 256, P1_SMEM>>>(x, sa_ptr);
    wsum_kernel<<<Bq * Kq, 256>>>(sa_ptr);
    phase2_kernel<<<dim3(Cq / 256, Bq, 8), 256, P2_SMEM>>>(x, sa_ptr);
    phase3_kernel<<<Bq * Kq, 128>>>(anchor);
    phase4_kernel<<<Bq, 256>>>(flat_ptr);
}

// round 10
// speedup vs baseline: 1.5917x; 1.0032x over previous
#include <cuda_runtime.h>
#include <cstdint>

#define Bq 16
#define Cq 512
#define Nq 4096
#define Kq 64

// ================= scratch (static device allocations only) =================
__device__ float4 gW4[64][512];       // per-8c-chunk W images: [chunk][k*8+pp] = (W1h,W2h,W1l,W2l)
__device__ float gInvS[Kq][Cq];
__device__ float gCst[Kq];
__device__ float g_sa[(size_t)Bq*Kq*Nq];
__device__ float g_wx8[8][Bq][Kq][Cq];
__device__ float g_wsum[Bq][Kq];
__device__ float g_row[Bq][Kq];
__device__ float g_nodes[Bq][Kq][Cq];

// ================= helpers =================
__device__ __forceinline__ float tf32hi(float v) {
    return __uint_as_float(__float_as_uint(v) & 0xFFFFE000u);
}
// 3-bit swizzle keyed on row bits 0..2 (phase1 W images)
__device__ __forceinline__ int swz(int row) {
    return ((row & 1) << 2) | (((row >> 1) & 1) << 1) | ((row >> 2) & 1);
}
__device__ __forceinline__ void mma8(float* d, const unsigned* a, const unsigned* b) {
    asm volatile(
        "mma.sync.aligned.m16n8k8.row.col.f32.tf32.tf32.f32 "
        "{%0,%1,%2,%3}, {%4,%5,%6,%7}, {%8,%9}, {%0,%1,%2,%3};"
        : "+f"(d[0]), "+f"(d[1]), "+f"(d[2]), "+f"(d[3])
        : "r"(a[0]), "r"(a[1]), "r"(a[2]), "r"(a[3]), "r"(b[0]), "r"(b[1]));
}
__device__ __forceinline__ uint32_t smem_u32(const void* p) {
    uint32_t a;
    asm("{ .reg .u64 t; cvta.to.shared.u64 t, %1; cvt.u32.u64 %0, t; }" : "=r"(a) : "l"(p));
    return a;
}
#define CP16(dst, src) asm volatile("cp.async.cg.shared.global [%0], [%1], 16;" :: "r"(dst), "l"(src))
#define CPCOMMIT()     asm volatile("cp.async.commit_group;" ::: "memory")
#define CPWAIT1()      asm volatile("cp.async.wait_group 1;" ::: "memory")
#define CPWAIT0()      asm volatile("cp.async.wait_group 0;" ::: "memory")

// ===== phase1: 3 buffers of { A raw x [16c][264f], B = 2 W sub-images (16KB) } =====
#define P1_BUF  33280u
#define P1_SMEM 99840
// ===== phase2: 3 buffers of { A raw x [256c][16n] swizzled, B raw sa [64k][16n] } =====
#define P2_BUF  20480u
#define P2_BOFF 16384u
#define P2_SMEM 61440

// ================= prep: sigma, W images, const =================
__global__ void prep_kernel(const float* __restrict__ anchor,
                            const float* __restrict__ sraw) {
    const int k = blockIdx.x;       // 64
    const int tid = threadIdx.x;    // 256
    float part = 0.f;
#pragma unroll
    for (int j = 0; j < 2; ++j) {
        int c = tid + j * 256;
        float sr = sraw[k * Cq + c];
        float sg = 1.f / (1.f + __expf(-sr));
        float a  = anchor[k * Cq + c];
        float i2 = 1.f / (sg * sg);
        float w2 = -2.f * a * i2;
        gInvS[k][c] = 1.f / sg;
        part += a * a * i2;
        int ch = c >> 3, p = c & 7;
        int pp = p ^ swz(k);
        float i2h = tf32hi(i2), w2h = tf32hi(w2);
        gW4[ch][k * 8 + pp] = make_float4(i2h, w2h, i2 - i2h, w2 - w2h);
    }
#pragma unroll
    for (int off = 16; off; off >>= 1) part += __shfl_xor_sync(0xffffffffu, part, off);
    __shared__ float red[8];
    if ((tid & 31) == 0) red[tid >> 5] = part;
    __syncthreads();
    if (tid == 0) {
        float s = 0.f;
#pragma unroll
        for (int i = 0; i < 8; ++i) s += red[i];
        gCst[k] = s;
    }
}

// ================= phase 1: distance GEMM (3xTF32 mma) + softmax =================
// block = (n-tile 256, b). warp tile 32n x 64k. 32 chunks of 16 c (4 mma steps each).
// 3-stage cp.async pipeline, one barrier per chunk.
__global__ __launch_bounds__(256, 2)
void phase1_kernel(const float* __restrict__ x, float* __restrict__ sa) {
    extern __shared__ char smem[];
    __shared__ float cst[64];
    const uint32_t sb = smem_u32(smem);
    const int tid = threadIdx.x;
    const int w = tid >> 5, lane = tid & 31;
    const int g = lane >> 2, q = lane & 3;
    const int n0w = w << 5;
    const int b  = blockIdx.y;
    const int n0 = blockIdx.x << 8;
    const float* xb = x + (size_t)b * Cq * Nq + n0;
    if (tid < 64) cst[tid] = gCst[tid];

    float acc[2][8][4];
#pragma unroll
    for (int i = 0; i < 2; ++i)
#pragma unroll
        for (int j = 0; j < 8; ++j)
#pragma unroll
            for (int e = 0; e < 4; ++e) acc[i][j][e] = 0.f;

    auto fill = [&](int ch) {
        const uint32_t base = sb + (uint32_t)(ch % 3) * P1_BUF;
        const float* xc = xb + (size_t)(ch << 4) * Nq;
        // A: 16 rows(c) x 256n -> 1024 x 16B (row pitch 1056B)
#pragma unroll
        for (int it = 0; it < 4; ++it) {
            int u = tid + (it << 8);
            int row = u >> 6, seg = u & 63;
            CP16(base + (uint32_t)row * 1056u + (uint32_t)(seg << 4),
                 xc + (size_t)row * Nq + (seg << 2));
        }
        // B: two W sub-images, contiguous 1024 float4
        const float4* wsrc = &gW4[ch << 1][0];
#pragma unroll
        for (int it = 0; it < 4; ++it) {
            int u = tid + (it << 8);
            CP16(base + 16896u + (uint32_t)(u << 4), wsrc + u);
        }
        CPCOMMIT();
    };

    auto gemm = [&](int buf) {
        const float* fA = (const float*)(smem + (uint32_t)buf * P1_BUF);
        const float4* fB = (const float4*)(smem + (uint32_t)buf * P1_BUF + 16896u);
#pragma unroll
        for (int s = 0; s < 4; ++s) {
            const int crow = (s << 2) + q;
            const float* arow = fA + crow * 264 + n0w + g;
            float v0 = arow[0], v1 = arow[8], v2 = arow[16], v3 = arow[24];
            unsigned ah[2][4], al[2][4];
            {
                float q0 = v0 * v0, q1 = v1 * v1, h;
                h = tf32hi(q0); ah[0][0] = __float_as_uint(h); al[0][0] = __float_as_uint(q0 - h);
                h = tf32hi(q1); ah[0][1] = __float_as_uint(h); al[0][1] = __float_as_uint(q1 - h);
                h = tf32hi(v0); ah[0][2] = __float_as_uint(h); al[0][2] = __float_as_uint(v0 - h);
                h = tf32hi(v1); ah[0][3] = __float_as_uint(h); al[0][3] = __float_as_uint(v1 - h);
                float q2 = v2 * v2, q3 = v3 * v3;
                h = tf32hi(q2); ah[1][0] = __float_as_uint(h); al[1][0] = __float_as_uint(q2 - h);
                h = tf32hi(q3); ah[1][1] = __float_as_uint(h); al[1][1] = __float_as_uint(q3 - h);
                h = tf32hi(v2); ah[1][2] = __float_as_uint(h); al[1][2] = __float_as_uint(v2 - h);
                h = tf32hi(v3); ah[1][3] = __float_as_uint(h); al[1][3] = __float_as_uint(v3 - h);
            }
            const float4* fBs = fB + (s >> 1) * 512;
            const int pl = ((s & 1) << 2) + q;
#pragma unroll
            for (int jh = 0; jh < 2; ++jh) {
                float4 fb[4];
#pragma unroll
                for (int jj = 0; jj < 4; ++jj) {
                    int k = (((jh << 2) + jj) << 3) + g;
                    fb[jj] = fBs[k * 8 + (pl ^ swz(k))];
                }
#pragma unroll
                for (int jj = 0; jj < 4; ++jj) {
                    unsigned bh[2] = { __float_as_uint(fb[jj].x), __float_as_uint(fb[jj].y) };
                    mma8(acc[0][(jh << 2) + jj], ah[0], bh);
                    mma8(acc[1][(jh << 2) + jj], ah[1], bh);
                }
#pragma unroll
                for (int jj = 0; jj < 4; ++jj) {
                    unsigned bl[2] = { __float_as_uint(fb[jj].z), __float_as_uint(fb[jj].w) };
                    mma8(acc[0][(jh << 2) + jj], ah[0], bl);
                    mma8(acc[1][(jh << 2) + jj], ah[1], bl);
                }
#pragma unroll
                for (int jj = 0; jj < 4; ++jj) {
                    unsigned bh[2] = { __float_as_uint(fb[jj].x), __float_as_uint(fb[jj].y) };
                    mma8(acc[0][(jh << 2) + jj], al[0], bh);
                    mma8(acc[1][(jh << 2) + jj], al[1], bh);
                }
            }
        }
    };

    fill(0); fill(1);
    for (int ch = 0; ch < 32; ++ch) {
        if (ch < 31) { CPWAIT1(); } else { CPWAIT0(); }
        __syncthreads();
        if (ch + 2 < 32) fill(ch + 2);
        gemm(ch % 3);
    }
    CPWAIT0();
    __syncthreads();

    // stage d2 in smem (overlays buffers)
    float* d2 = (float*)smem;
#pragma unroll
    for (int i = 0; i < 2; ++i) {
        int r0 = n0w + (i << 4) + g;
#pragma unroll
        for (int j = 0; j < 8; ++j) {
            int kc = (j << 3) + (q << 1);
            *(float2*)&d2[r0 * 66 + kc]       = make_float2(acc[i][j][0], acc[i][j][1]);
            *(float2*)&d2[(r0 + 8) * 66 + kc] = make_float2(acc[i][j][2], acc[i][j][3]);
        }
    }
    __syncthreads();

    // softmax: one thread per n
    {
        float e[64];
#pragma unroll
        for (int k = 0; k < 64; ++k) e[k] = d2[tid * 66 + k] + cst[k];
        float mn = e[0];
#pragma unroll
        for (int k = 1; k < 64; ++k) mn = fminf(mn, e[k]);
        float s = 0.f;
#pragma unroll
        for (int k = 0; k < 64; ++k) {
            float t = __expf(-0.5f * (e[k] - mn));
            e[k] = t;
            s += t;
        }
        float r = 1.f / s;
        float* sp = sa + (size_t)b * Kq * Nq + n0 + tid;
#pragma unroll
        for (int k = 0; k < 64; ++k) sp[(size_t)k * Nq] = e[k] * r;
    }
}

// ================= w_sum =================
__global__ void wsum_kernel(const float* __restrict__ sa) {
    const int bk = blockIdx.x;      // 1024
    const int tid = threadIdx.x;    // 256
    const float4* row = reinterpret_cast<const float4*>(sa + (size_t)bk * Nq);
    float s = 0.f;
#pragma unroll
    for (int i = 0; i < 4; ++i) {
        float4 v = row[tid + i * 256];
        s += (v.x + v.y) + (v.z + v.w);
    }
#pragma unroll
    for (int off = 16; off; off >>= 1) s += __shfl_xor_sync(0xffffffffu, s, off);
    __shared__ float red[8];
    if ((tid & 31) == 0) red[tid >> 5] = s;
    __syncthreads();
    if (tid == 0) {
        float t = 0.f;
#pragma unroll
        for (int i = 0; i < 8; ++i) t += red[i];
        g_wsum[bk >> 6][bk & 63] = t;
    }
}

// ================= phase 2: wx[c,k] = sum_n x[c,n]*sa[k,n] (3xTF32 mma) =================
// grid (2 ctile, 16 b, 8 seg). block tile 256c x 64k, 32 chunks of 16 n (2 steps each).
// 3-stage cp.async pipeline, one barrier per chunk. 64B rows with 16B-seg XOR swizzle.
__global__ __launch_bounds__(256, 2)
void phase2_kernel(const float* __restrict__ x, const float* __restrict__ sa) {
    extern __shared__ char smem[];
    const uint32_t sb = smem_u32(smem);
    const int tid = threadIdx.x;
    const int w = tid >> 5, lane = tid & 31;
    const int g = lane >> 2, q = lane & 3;
    const int c0w = w << 5;
    const int c0 = (int)blockIdx.x << 8;
    const int b  = blockIdx.y;
    const int seg = blockIdx.z;
    const int n0 = seg << 9;
    const float* xb = x  + ((size_t)b * Cq + c0) * Nq + n0;
    const float* sbp = sa + (size_t)b * Kq * Nq + n0;

    float acc[2][8][4];
#pragma unroll
    for (int i = 0; i < 2; ++i)
#pragma unroll
        for (int j = 0; j < 8; ++j)
#pragma unroll
            for (int e = 0; e < 4; ++e) acc[i][j][e] = 0.f;

    auto fill = [&](int ch) {
        const uint32_t base = sb + (uint32_t)(ch % 3) * P2_BUF;
        const int nn = ch << 4;
        // A: 256 rows(c) x 16n -> 1024 x 16B, swizzled segs
#pragma unroll
        for (int it = 0; it < 4; ++it) {
            int u = tid + (it << 8);
            int row = u >> 2, sg2 = u & 3;
            CP16(base + (uint32_t)(row << 6) + (uint32_t)((sg2 ^ ((row >> 1) & 3)) << 4),
                 xb + (size_t)row * Nq + nn + (sg2 << 2));
        }
        // B: 64 rows(k) x 16n -> 256 x 16B
        {
            int row = tid >> 2, sg2 = tid & 3;
            CP16(base + P2_BOFF + (uint32_t)(row << 6) + (uint32_t)((sg2 ^ ((row >> 1) & 3)) << 4),
                 sbp + (size_t)row * Nq + nn + (sg2 << 2));
        }
        CPCOMMIT();
    };

    auto gemm = [&](int buf) {
        const float* fA = (const float*)(smem + (uint32_t)buf * P2_BUF);
        const float* fB = (const float*)(smem + (uint32_t)buf * P2_BUF + P2_BOFF);
#pragma unroll
        for (int s = 0; s < 2; ++s) {
            const int w0 = (s << 3) + q;       // word within 16-word row
            unsigned ah[2][4], al[2][4];
#pragma unroll
            for (int i = 0; i < 2; ++i) {
                int r0 = c0w + (i << 4) + g;
                int r1 = r0 + 8;
                int k0 = ((r0 >> 1) & 3) << 2;
                int k1 = ((r1 >> 1) & 3) << 2;
                float x0 = fA[(r0 << 4) + (w0 ^ k0)];
                float x1 = fA[(r1 << 4) + (w0 ^ k1)];
                float x2 = fA[(r0 << 4) + ((w0 + 4) ^ k0)];
                float x3 = fA[(r1 << 4) + ((w0 + 4) ^ k1)];
                float h;
                h = tf32hi(x0); ah[i][0] = __float_as_uint(h); al[i][0] = __float_as_uint(x0 - h);
                h = tf32hi(x1); ah[i][1] = __float_as_uint(h); al[i][1] = __float_as_uint(x1 - h);
                h = tf32hi(x2); ah[i][2] = __float_as_uint(h); al[i][2] = __float_as_uint(x2 - h);
                h = tf32hi(x3); ah[i][3] = __float_as_uint(h); al[i][3] = __float_as_uint(x3 - h);
            }
#pragma unroll
            for (int jh = 0; jh < 2; ++jh) {
                unsigned bh[4][2], bl[4][2];
#pragma unroll
                for (int jj = 0; jj < 4; ++jj) {
                    int k = (((jh << 2) + jj) << 3) + g;
                    int kk = ((k >> 1) & 3) << 2;
                    float y0 = fB[(k << 4) + (w0 ^ kk)];
                    float y1 = fB[(k << 4) + ((w0 + 4) ^ kk)];
                    float h;
                    h = tf32hi(y0); bh[jj][0] = __float_as_uint(h); bl[jj][0] = __float_as_uint(y0 - h);
                    h = tf32hi(y1); bh[jj][1] = __float_as_uint(h); bl[jj][1] = __float_as_uint(y1 - h);
                }
#pragma unroll
                for (int jj = 0; jj < 4; ++jj) {
                    mma8(acc[0][(jh << 2) + jj], ah[0], bh[jj]);
                    mma8(acc[1][(jh << 2) + jj], ah[1], bh[jj]);
                }
#pragma unroll
                for (int jj = 0; jj < 4; ++jj) {
                    mma8(acc[0][(jh << 2) + jj], ah[0], bl[jj]);
                    mma8(acc[1][(jh << 2) + jj], ah[1], bl[jj]);
                }
#pragma unroll
                for (int jj = 0; jj < 4; ++jj) {
                    mma8(acc[0][(jh << 2) + jj], al[0], bh[jj]);
                    mma8(acc[1][(jh << 2) + jj], al[1], bh[jj]);
                }
            }
        }
    };

    fill(0); fill(1);
    for (int ch = 0; ch < 32; ++ch) {
        if (ch < 31) { CPWAIT1(); } else { CPWAIT0(); }
        __syncthreads();
        if (ch + 2 < 32) fill(ch + 2);
        gemm(ch % 3);
    }

    // epilogue: scatter D[c,k] partials
    float* basep = &g_wx8[seg][b][0][0];
#pragma unroll
    for (int i = 0; i < 2; ++i) {
        int cc = c0 + c0w + (i << 4) + g;
#pragma unroll
        for (int j = 0; j < 8; ++j) {
            int kc = (j << 3) + (q << 1);
            basep[(size_t)kc * Cq + cc]           = acc[i][j][0];
            basep[(size_t)(kc + 1) * Cq + cc]     = acc[i][j][1];
            basep[(size_t)kc * Cq + cc + 8]       = acc[i][j][2];
            basep[(size_t)(kc + 1) * Cq + cc + 8] = acc[i][j][3];
        }
    }
}

// ================= phase 3: nodes + per-row l2norm =================
__global__ void phase3_kernel(const float* __restrict__ anchor) {
    const int bk = blockIdx.x;     // 1024
    const int b = bk >> 6, k = bk & 63;
    const int tid = threadIdx.x;   // 128
    const float wsv = g_wsum[b][k];
    const float invw = 1.f / (wsv + 1e-9f);
    float t[4];
    float ssq = 0.f;
#pragma unroll
    for (int j = 0; j < 4; ++j) {
        int c = tid + j * 128;
        float wx = 0.f;
#pragma unroll
        for (int s = 0; s < 8; ++s) wx += g_wx8[s][b][k][c];
        float nd = (wx - wsv * anchor[k * Cq + c]) * gInvS[k][c] * invw;
        t[j] = nd;
        ssq += nd * nd;
    }
#pragma unroll
    for (int off = 16; off; off >>= 1) ssq += __shfl_xor_sync(0xffffffffu, ssq, off);
    __shared__ float red[4];
    __shared__ float totsh;
    if ((tid & 31) == 0) red[tid >> 5] = ssq;
    __syncthreads();
    if (tid == 0) totsh = red[0] + red[1] + red[2] + red[3];
    __syncthreads();
    float total = totsh;
    float scale = 1.f / fmaxf(sqrtf(total), 1e-12f);
#pragma unroll
    for (int j = 0; j < 4; ++j) {
        int c = tid + j * 128;
        g_nodes[b][k][c] = t[j] * scale;
    }
    if (tid == 0) g_row[b][k] = total * scale * scale;
}

// ================= phase 4: global l2norm + output =================
__global__ void phase4_kernel(float* __restrict__ outflat) {
    const int b = blockIdx.x;      // 16
    const int tid = threadIdx.x;   // 256
    __shared__ float red[64];
    __shared__ float gsh;
    if (tid < 64) red[tid] = g_row[b][tid];
    __syncthreads();
    if (tid == 0) {
        float s = 0.f;
#pragma unroll
        for (int i = 0; i < 64; ++i) s += red[i];
        gsh = 1.f / fmaxf(sqrtf(s), 1e-12f);
    }
    __syncthreads();
    float g = gsh;
    const float* np = &g_nodes[b][0][0];
    float* op = outflat + (size_t)b * Kq * Cq;
    for (int i = tid; i < Kq * Cq; i += 256) op[i] = np[i] * g;
}

// ================= launch =================
extern "C" void kernel_launch(void* const* d_in, const int* in_sizes, int n_in,
                              void* d_out, int out_size) {
    const float* x      = (const float*)d_in[0];
    const float* anchor = (const float*)d_in[1];
    const float* sraw   = (const float*)d_in[2];
    float* outf = (float*)d_out;

    const int FLAT = Bq * Cq * Kq;      // 524288
    const int SA   = Bq * Kq * Nq;      // 4194304

    float* sa_dev = nullptr;
    cudaGetSymbolAddress((void**)&sa_dev, g_sa);
    float* nodes_dev = nullptr;
    cudaGetSymbolAddress((void**)&nodes_dev, g_nodes);

    float* sa_ptr;
    float* flat_ptr;
    if (out_size == FLAT) {
        flat_ptr = outf;
        sa_ptr = sa_dev;
    } else if (out_size == SA) {
        sa_ptr = outf;
        flat_ptr = nodes_dev;
    } else {
        flat_ptr = outf;
        sa_ptr = outf + FLAT;
    }

    static bool attr_done = false;
    if (!attr_done) {
        cudaFuncSetAttribute(phase1_kernel,
                             cudaFuncAttributeMaxDynamicSharedMemorySize, P1_SMEM);
        cudaFuncSetAttribute(phase2_kernel,
                             cudaFuncAttributeMaxDynamicSharedMemorySize, P2_SMEM);
        attr_done = true;
    }

    prep_kernel<<<Kq, 256>>>(anchor, sraw);
    phase1_kernel<<<dim3(Nq / 256, Bq), 256, P1_SMEM>>>(x, sa_ptr);
    wsum_kernel<<<Bq * Kq, 256>>>(sa_ptr);
    phase2_kernel<<<dim3(Cq / 256, Bq, 8), 256, P2_SMEM>>>(x, sa_ptr);
    phase3_kernel<<<Bq * Kq, 128>>>(anchor);
    phase4_kernel<<<Bq, 256>>>(flat_ptr);
}

// round 11
// speedup vs baseline: 2.1743x; 1.3661x over previous
#include <cuda_runtime.h>
#include <cstdint>

#define Bq 16
#define Cq 512
#define Nq 4096
#define Kq 64

// ================= scratch (static device allocations only) =================
__device__ uint4 gW16[32][512];            // per-16c-chunk fp16 W images (8KB each)
__device__ float gInvS[Kq][Cq];
__device__ float gCst[Kq];
__device__ float g_sa[(size_t)Bq*Kq*Nq];
__device__ uint4 g_sa16[(size_t)Bq*Kq*256*4];  // [b*64+k][256 chunks][4 q] 16B blocks
__device__ float g_fk[Bq*Kq];
__device__ float g_invf[Bq*Kq];
__device__ float g_wx8[8][Bq][Kq][Cq];
__device__ float g_wsum[Bq][Kq];
__device__ float g_row[Bq][Kq];
__device__ float g_nodes[Bq][Kq][Cq];

// ================= helpers =================
__device__ __forceinline__ unsigned pk2h(float lo, float hi) {
    unsigned d;
    asm("cvt.rn.f16x2.f32 %0, %1, %2;" : "=r"(d) : "f"(hi), "f"(lo));
    return d;
}
__device__ __forceinline__ float2 unpk2h(unsigned u) {
    float lo, hi;
    asm("{.reg .f16 a,b; mov.b32 {a,b}, %2; cvt.f32.f16 %0, a; cvt.f32.f16 %1, b;}"
        : "=f"(lo), "=f"(hi) : "r"(u));
    return make_float2(lo, hi);
}
// split pair (v0=even slot, v1=odd slot) into fp16x2 hi and lo regs
__device__ __forceinline__ void splitpair(float v0, float v1, unsigned& h, unsigned& l) {
    h = pk2h(v0, v1);
    float2 f = unpk2h(h);
    l = pk2h(v0 - f.x, v1 - f.y);
}
__device__ __forceinline__ void mmaH(float* d, const unsigned* a, const unsigned* b) {
    asm volatile(
        "mma.sync.aligned.m16n8k16.row.col.f32.f16.f16.f32 "
        "{%0,%1,%2,%3}, {%4,%5,%6,%7}, {%8,%9}, {%0,%1,%2,%3};"
        : "+f"(d[0]), "+f"(d[1]), "+f"(d[2]), "+f"(d[3])
        : "r"(a[0]), "r"(a[1]), "r"(a[2]), "r"(a[3]), "r"(b[0]), "r"(b[1]));
}
__device__ __forceinline__ uint32_t smem_u32(const void* p) {
    uint32_t a;
    asm("{ .reg .u64 t; cvta.to.shared.u64 t, %1; cvt.u32.u64 %0, t; }" : "=r"(a) : "l"(p));
    return a;
}
#define CP16(dst, src) asm volatile("cp.async.cg.shared.global [%0], [%1], 16;" :: "r"(dst), "l"(src))
#define CPCOMMIT()     asm volatile("cp.async.commit_group;" ::: "memory")
#define CPWAIT1()      asm volatile("cp.async.wait_group 1;" ::: "memory")
#define CPWAIT0()      asm volatile("cp.async.wait_group 0;" ::: "memory")

// ===== phase1: 3 bufs of { A raw x [16c][260f pitch], B fp16 image 8KB } =====
#define P1_BUF   24832u
#define P1_BOFF  16640u
#define P1_SMEM  74496
// ===== phase2: 3 bufs of { A raw x [256c][16n] swizzled 16KB, B sa16 4KB } =====
#define P2_BUF   20480u
#define P2_BOFF  16384u
#define P2_SMEM  61440

// ================= prep: sigma, fp16 W images, const =================
__global__ void prep_kernel(const float* __restrict__ anchor,
                            const float* __restrict__ sraw) {
    const int k = blockIdx.x;       // 64
    const int tid = threadIdx.x;    // 256
    float part = 0.f;
#pragma unroll
    for (int jj = 0; jj < 2; ++jj) {
        int c = tid + jj * 256;
        float sr = sraw[k * Cq + c];
        float sg = 1.f / (1.f + __expf(-sr));
        float a  = anchor[k * Cq + c];
        float i2 = 1.f / (sg * sg);
        float w2 = -2.f * a * i2;
        gInvS[k][c] = 1.f / sg;
        part += a * a * i2;
        int ch = c >> 4, cl = c & 15;
        int j = k >> 3, gg = k & 7;
        int q = (cl >> 1) & 3, reg = cl >> 3, half = cl & 1;
        // step0 = x^2 weight (inv_s2), step1 = x weight (-2a*inv_s2)
        float vals[2] = { i2, w2 };
#pragma unroll
        for (int s = 0; s < 2; ++s) {
            unsigned hp, lp;
            splitpair(vals[s], 0.f, hp, lp);
            unsigned short* base =
                (unsigned short*)&gW16[ch][(((s * 8 + j) * 8 + gg) * 4 + q)];
            base[reg * 2 + half]     = (unsigned short)(hp & 0xFFFFu);
            base[4 + reg * 2 + half] = (unsigned short)(lp & 0xFFFFu);
        }
    }
#pragma unroll
    for (int off = 16; off; off >>= 1) part += __shfl_xor_sync(0xffffffffu, part, off);
    __shared__ float red[8];
    if ((tid & 31) == 0) red[tid >> 5] = part;
    __syncthreads();
    if (tid == 0) {
        float s = 0.f;
#pragma unroll
        for (int i = 0; i < 8; ++i) s += red[i];
        gCst[k] = s;
    }
}

// ================= phase 1: distance GEMM (3xFP16 mma) + softmax =================
// block = (n-tile 256, b). warp tile 32n x 64k. 32 chunks of 16 c (2 k16 steps each).
__global__ __launch_bounds__(256, 2)
void phase1_kernel(const float* __restrict__ x, float* __restrict__ sa) {
    extern __shared__ char smem[];
    __shared__ float cst[64];
    const uint32_t sb = smem_u32(smem);
    const int tid = threadIdx.x;
    const int w = tid >> 5, lane = tid & 31;
    const int g = lane >> 2, q = lane & 3;
    const int n0w = w << 5;
    const int b  = blockIdx.y;
    const int n0 = blockIdx.x << 8;
    const float* xb = x + (size_t)b * Cq * Nq + n0;
    if (tid < 64) cst[tid] = gCst[tid];

    float acc[2][8][4];
#pragma unroll
    for (int i = 0; i < 2; ++i)
#pragma unroll
        for (int j = 0; j < 8; ++j)
#pragma unroll
            for (int e = 0; e < 4; ++e) acc[i][j][e] = 0.f;

    auto fill = [&](int ch) {
        const uint32_t base = sb + (uint32_t)(ch % 3) * P1_BUF;
        const float* xc = xb + (size_t)(ch << 4) * Nq;
        // A: 16 rows(c) x 256n, row pitch 1040B
#pragma unroll
        for (int it = 0; it < 4; ++it) {
            int u = tid + (it << 8);
            int row = u >> 6, seg = u & 63;
            CP16(base + (uint32_t)row * 1040u + (uint32_t)(seg << 4),
                 xc + (size_t)row * Nq + (seg << 2));
        }
        // B: fp16 image, 512 uint4
#pragma unroll
        for (int it = 0; it < 2; ++it) {
            int u = tid + (it << 8);
            CP16(base + P1_BOFF + (uint32_t)(u << 4), &gW16[ch][u]);
        }
        CPCOMMIT();
    };

    auto gemm = [&](int buf) {
        const float* fA = (const float*)(smem + (uint32_t)buf * P1_BUF);
        const uint4* fB = (const uint4*)(smem + (uint32_t)buf * P1_BUF + P1_BOFF);
        float xv[2][8];
#pragma unroll
        for (int i = 0; i < 2; ++i) {
            const float* pa = fA + n0w + (i << 4) + g;
            xv[i][0] = pa[(2 * q) * 260];       xv[i][1] = pa[(2 * q + 1) * 260];
            xv[i][2] = pa[(2 * q + 8) * 260];   xv[i][3] = pa[(2 * q + 9) * 260];
            xv[i][4] = pa[(2 * q) * 260 + 8];   xv[i][5] = pa[(2 * q + 1) * 260 + 8];
            xv[i][6] = pa[(2 * q + 8) * 260 + 8]; xv[i][7] = pa[(2 * q + 9) * 260 + 8];
        }
#pragma unroll
        for (int s = 0; s < 2; ++s) {
            unsigned aH[2][4], aL[2][4];
#pragma unroll
            for (int i = 0; i < 2; ++i) {
                float e0, e1, e2, e3, e4, e5, e6, e7;
                if (s == 0) {
                    e0 = xv[i][0] * xv[i][0]; e1 = xv[i][1] * xv[i][1];
                    e2 = xv[i][2] * xv[i][2]; e3 = xv[i][3] * xv[i][3];
                    e4 = xv[i][4] * xv[i][4]; e5 = xv[i][5] * xv[i][5];
                    e6 = xv[i][6] * xv[i][6]; e7 = xv[i][7] * xv[i][7];
                } else {
                    e0 = xv[i][0]; e1 = xv[i][1]; e2 = xv[i][2]; e3 = xv[i][3];
                    e4 = xv[i][4]; e5 = xv[i][5]; e6 = xv[i][6]; e7 = xv[i][7];
                }
                splitpair(e0, e1, aH[i][0], aL[i][0]);   // row r,   slots 2q,2q+1
                splitpair(e4, e5, aH[i][1], aL[i][1]);   // row r+8, slots 2q,2q+1
                splitpair(e2, e3, aH[i][2], aL[i][2]);   // row r,   slots 2q+8,2q+9
                splitpair(e6, e7, aH[i][3], aL[i][3]);   // row r+8
            }
#pragma unroll
            for (int jb = 0; jb < 2; ++jb) {
                uint4 w4[4];
#pragma unroll
                for (int jj = 0; jj < 4; ++jj)
                    w4[jj] = fB[(((s * 8 + (jb << 2) + jj) * 8 + g) << 2) + q];
#pragma unroll
                for (int jj = 0; jj < 4; ++jj) {
                    unsigned bh[2] = { w4[jj].x, w4[jj].y };
                    mmaH(acc[0][(jb << 2) + jj], aH[0], bh);
                    mmaH(acc[1][(jb << 2) + jj], aH[1], bh);
                }
#pragma unroll
                for (int jj = 0; jj < 4; ++jj) {
                    unsigned bl[2] = { w4[jj].z, w4[jj].w };
                    mmaH(acc[0][(jb << 2) + jj], aH[0], bl);
                    mmaH(acc[1][(jb << 2) + jj], aH[1], bl);
                }
#pragma unroll
                for (int jj = 0; jj < 4; ++jj) {
                    unsigned bh[2] = { w4[jj].x, w4[jj].y };
                    mmaH(acc[0][(jb << 2) + jj], aL[0], bh);
                    mmaH(acc[1][(jb << 2) + jj], aL[1], bh);
                }
            }
        }
    };

    fill(0); fill(1);
    for (int ch = 0; ch < 32; ++ch) {
        if (ch < 31) { CPWAIT1(); } else { CPWAIT0(); }
        __syncthreads();
        if (ch + 2 < 32) fill(ch + 2);
        gemm(ch % 3);
    }
    CPWAIT0();
    __syncthreads();

    // stage d2 in smem (overlays buffers)
    float* d2 = (float*)smem;
#pragma unroll
    for (int i = 0; i < 2; ++i) {
        int r0 = n0w + (i << 4) + g;
#pragma unroll
        for (int j = 0; j < 8; ++j) {
            int kc = (j << 3) + (q << 1);
            *(float2*)&d2[r0 * 66 + kc]       = make_float2(acc[i][j][0], acc[i][j][1]);
            *(float2*)&d2[(r0 + 8) * 66 + kc] = make_float2(acc[i][j][2], acc[i][j][3]);
        }
    }
    __syncthreads();

    // softmax: one thread per n
    {
        float e[64];
#pragma unroll
        for (int k = 0; k < 64; ++k) e[k] = d2[tid * 66 + k] + cst[k];
        float mn = e[0];
#pragma unroll
        for (int k = 1; k < 64; ++k) mn = fminf(mn, e[k]);
        float s = 0.f;
#pragma unroll
        for (int k = 0; k < 64; ++k) {
            float t = __expf(-0.5f * (e[k] - mn));
            e[k] = t;
            s += t;
        }
        float r = 1.f / s;
        float* sp = sa + (size_t)b * Kq * Nq + n0 + tid;
#pragma unroll
        for (int k = 0; k < 64; ++k) sp[(size_t)k * Nq] = e[k] * r;
    }
}

// ================= w_sum + per-(b,k) scale factor =================
__global__ void wsum_kernel(const float* __restrict__ sa) {
    const int bk = blockIdx.x;      // 1024
    const int tid = threadIdx.x;    // 256
    const float4* row = reinterpret_cast<const float4*>(sa + (size_t)bk * Nq);
    float s = 0.f, m = 0.f;
#pragma unroll
    for (int i = 0; i < 4; ++i) {
        float4 v = row[tid + i * 256];
        s += (v.x + v.y) + (v.z + v.w);
        m = fmaxf(m, fmaxf(fmaxf(v.x, v.y), fmaxf(v.z, v.w)));
    }
#pragma unroll
    for (int off = 16; off; off >>= 1) {
        s += __shfl_xor_sync(0xffffffffu, s, off);
        m = fmaxf(m, __shfl_xor_sync(0xffffffffu, m, off));
    }
    __shared__ float red[8], redm[8];
    if ((tid & 31) == 0) { red[tid >> 5] = s; redm[tid >> 5] = m; }
    __syncthreads();
    if (tid == 0) {
        float t = 0.f, mm = 0.f;
#pragma unroll
        for (int i = 0; i < 8; ++i) { t += red[i]; mm = fmaxf(mm, redm[i]); }
        g_wsum[bk >> 6][bk & 63] = t;
        int e = (mm > 0.f) ? ilogbf(mm) : 0;
        g_fk[bk]   = exp2f((float)(-e));
        g_invf[bk] = exp2f((float)(e));
    }
}

// ================= sa -> scaled pre-split fp16 (sa16) =================
__global__ void sa16_kernel(const float* __restrict__ sa) {
    const int bk = blockIdx.x;      // 1024
    const int t = threadIdx.x;      // 256, one 16n chunk each
    const float f = g_fk[bk];
    const float4* src = (const float4*)(sa + (size_t)bk * Nq + (size_t)t * 16);
    float v[16];
#pragma unroll
    for (int i = 0; i < 4; ++i) {
        float4 a = src[i];
        v[4 * i + 0] = a.x * f; v[4 * i + 1] = a.y * f;
        v[4 * i + 2] = a.z * f; v[4 * i + 3] = a.w * f;
    }
    uint4* dst = &g_sa16[((size_t)bk * 256 + t) * 4];
#pragma unroll
    for (int qq = 0; qq < 4; ++qq) {
        unsigned h0, l0, h1, l1;
        splitpair(v[2 * qq], v[2 * qq + 1], h0, l0);
        splitpair(v[2 * qq + 8], v[2 * qq + 9], h1, l1);
        uint4 o; o.x = h0; o.y = h1; o.z = l0; o.w = l1;
        dst[qq] = o;
    }
}

// ================= phase 2: wx[c,k] = sum_n x[c,n]*sa[k,n] (3xFP16 mma) =================
// grid (2 ctile, 16 b, 8 seg). block tile 256c x 64k, 32 chunks of 16 n (1 k16 step).
__global__ __launch_bounds__(256, 2)
void phase2_kernel(const float* __restrict__ x, const float* __restrict__ dummy) {
    extern __shared__ char smem[];
    const uint32_t sb = smem_u32(smem);
    const int tid = threadIdx.x;
    const int w = tid >> 5, lane = tid & 31;
    const int g = lane >> 2, q = lane & 3;
    const int c0w = w << 5;
    const int c0 = (int)blockIdx.x << 8;
    const int b  = blockIdx.y;
    const int seg = blockIdx.z;
    const int n0 = seg << 9;
    const float* xb = x + ((size_t)b * Cq + c0) * Nq + n0;

    float acc[2][8][4];
#pragma unroll
    for (int i = 0; i < 2; ++i)
#pragma unroll
        for (int j = 0; j < 8; ++j)
#pragma unroll
            for (int e = 0; e < 4; ++e) acc[i][j][e] = 0.f;

    auto fill = [&](int ch) {
        const uint32_t base = sb + (uint32_t)(ch % 3) * P2_BUF;
        const int nn = ch << 4;
        // A: 256 rows(c) x 16n, 64B rows with 16B-seg XOR swizzle
#pragma unroll
        for (int it = 0; it < 4; ++it) {
            int u = tid + (it << 8);
            int row = u >> 2, sg2 = u & 3;
            CP16(base + (uint32_t)(row << 6) + (uint32_t)((sg2 ^ ((row >> 1) & 3)) << 4),
                 xb + (size_t)row * Nq + nn + (sg2 << 2));
        }
        // B: pre-split sa16, 256 x 16B
        {
            int node = tid >> 2, qq = tid & 3;
            CP16(base + P2_BOFF + (uint32_t)(tid << 4),
                 &g_sa16[(((size_t)(b * 64 + node)) * 256 + (size_t)(seg * 32 + ch)) * 4 + qq]);
        }
        CPCOMMIT();
    };

    auto gemm = [&](int buf) {
        const float* fA = (const float*)(smem + (uint32_t)buf * P2_BUF);
        const uint4* fB = (const uint4*)(smem + (uint32_t)buf * P2_BUF + P2_BOFF);
        unsigned aH[2][4], aL[2][4];
#pragma unroll
        for (int i = 0; i < 2; ++i) {
            int r0 = c0w + (i << 4) + g;
            int r1 = r0 + 8;
            int k0 = ((r0 >> 1) & 3) << 2;
            int k1 = ((r1 >> 1) & 3) << 2;
            float2 p00 = *(const float2*)(fA + (r0 << 4) + ((2 * q) ^ k0));
            float2 p01 = *(const float2*)(fA + (r0 << 4) + ((2 * q + 8) ^ k0));
            float2 p10 = *(const float2*)(fA + (r1 << 4) + ((2 * q) ^ k1));
            float2 p11 = *(const float2*)(fA + (r1 << 4) + ((2 * q + 8) ^ k1));
            splitpair(p00.x, p00.y, aH[i][0], aL[i][0]);
            splitpair(p10.x, p10.y, aH[i][1], aL[i][1]);
            splitpair(p01.x, p01.y, aH[i][2], aL[i][2]);
            splitpair(p11.x, p11.y, aH[i][3], aL[i][3]);
        }
#pragma unroll
        for (int jb = 0; jb < 2; ++jb) {
            uint4 w4[4];
#pragma unroll
            for (int jj = 0; jj < 4; ++jj)
                w4[jj] = fB[(((((jb << 2) + jj) << 3) + g) << 2) + q];
#pragma unroll
            for (int jj = 0; jj < 4; ++jj) {
                unsigned bh[2] = { w4[jj].x, w4[jj].y };
                mmaH(acc[0][(jb << 2) + jj], aH[0], bh);
                mmaH(acc[1][(jb << 2) + jj], aH[1], bh);
            }
#pragma unroll
            for (int jj = 0; jj < 4; ++jj) {
                unsigned bl[2] = { w4[jj].z, w4[jj].w };
                mmaH(acc[0][(jb << 2) + jj], aH[0], bl);
                mmaH(acc[1][(jb << 2) + jj], aH[1], bl);
            }
#pragma unroll
            for (int jj = 0; jj < 4; ++jj) {
                unsigned bh[2] = { w4[jj].x, w4[jj].y };
                mmaH(acc[0][(jb << 2) + jj], aL[0], bh);
                mmaH(acc[1][(jb << 2) + jj], aL[1], bh);
            }
        }
    };

    fill(0); fill(1);
    for (int ch = 0; ch < 32; ++ch) {
        if (ch < 31) { CPWAIT1(); } else { CPWAIT0(); }
        __syncthreads();
        if (ch + 2 < 32) fill(ch + 2);
        gemm(ch % 3);
    }

    // epilogue: unscale by exact power-of-2 invf, scatter D[c,k] partials
    float* basep = &g_wx8[seg][b][0][0];
#pragma unroll
    for (int j = 0; j < 8; ++j) {
        int kc = (j << 3) + (q << 1);
        float f0 = g_invf[b * 64 + kc];
        float f1 = g_invf[b * 64 + kc + 1];
#pragma unroll
        for (int i = 0; i < 2; ++i) {
            int cc = c0 + c0w + (i << 4) + g;
            basep[(size_t)kc * Cq + cc]           = acc[i][j][0] * f0;
            basep[(size_t)(kc + 1) * Cq + cc]     = acc[i][j][1] * f1;
            basep[(size_t)kc * Cq + cc + 8]       = acc[i][j][2] * f0;
            basep[(size_t)(kc + 1) * Cq + cc + 8] = acc[i][j][3] * f1;
        }
    }
}

// ================= phase 3: nodes + per-row l2norm =================
__global__ void phase3_kernel(const float* __restrict__ anchor) {
    const int bk = blockIdx.x;     // 1024
    const int b = bk >> 6, k = bk & 63;
    const int tid = threadIdx.x;   // 128
    const float wsv = g_wsum[b][k];
    const float invw = 1.f / (wsv + 1e-9f);
    float t[4];
    float ssq = 0.f;
#pragma unroll
    for (int j = 0; j < 4; ++j) {
        int c = tid + j * 128;
        float wx = 0.f;
#pragma unroll
        for (int s = 0; s < 8; ++s) wx += g_wx8[s][b][k][c];
        float nd = (wx - wsv * anchor[k * Cq + c]) * gInvS[k][c] * invw;
        t[j] = nd;
        ssq += nd * nd;
    }
#pragma unroll
    for (int off = 16; off; off >>= 1) ssq += __shfl_xor_sync(0xffffffffu, ssq, off);
    __shared__ float red[4];
    __shared__ float totsh;
    if ((tid & 31) == 0) red[tid >> 5] = ssq;
    __syncthreads();
    if (tid == 0) totsh = red[0] + red[1] + red[2] + red[3];
    __syncthreads();
    float total = totsh;
    float scale = 1.f / fmaxf(sqrtf(total), 1e-12f);
#pragma unroll
    for (int j = 0; j < 4; ++j) {
        int c = tid + j * 128;
        g_nodes[b][k][c] = t[j] * scale;
    }
    if (tid == 0) g_row[b][k] = total * scale * scale;
}

// ================= phase 4: global l2norm + output =================
__global__ void phase4_kernel(float* __restrict__ outflat) {
    const int b = blockIdx.x;      // 16
    const int tid = threadIdx.x;   // 256
    __shared__ float red[64];
    __shared__ float gsh;
    if (tid < 64) red[tid] = g_row[b][tid];
    __syncthreads();
    if (tid == 0) {
        float s = 0.f;
#pragma unroll
        for (int i = 0; i < 64; ++i) s += red[i];
        gsh = 1.f / fmaxf(sqrtf(s), 1e-12f);
    }
    __syncthreads();
    float g = gsh;
    const float* np = &g_nodes[b][0][0];
    float* op = outflat + (size_t)b * Kq * Cq;
    for (int i = tid; i < Kq * Cq; i += 256) op[i] = np[i] * g;
}

// ================= launch =================
extern "C" void kernel_launch(void* const* d_in, const int* in_sizes, int n_in,
                              void* d_out, int out_size) {
    const float* x      = (const float*)d_in[0];
    const float* anchor = (const float*)d_in[1];
    const float* sraw   = (const float*)d_in[2];
    float* outf = (float*)d_out;

    const int FLAT = Bq * Cq * Kq;      // 524288
    const int SA   = Bq * Kq * Nq;      // 4194304

    float* sa_dev = nullptr;
    cudaGetSymbolAddress((void**)&sa_dev, g_sa);
    float* nodes_dev = nullptr;
    cudaGetSymbolAddress((void**)&nodes_dev, g_nodes);

    float* sa_ptr;
    float* flat_ptr;
    if (out_size == FLAT) {
        flat_ptr = outf;
        sa_ptr = sa_dev;
    } else if (out_size == SA) {
        sa_ptr = outf;
        flat_ptr = nodes_dev;
    } else {
        flat_ptr = outf;
        sa_ptr = outf + FLAT;
    }

    static bool attr_done = false;
    if (!attr_done) {
        cudaFuncSetAttribute(phase1_kernel,
                             cudaFuncAttributeMaxDynamicSharedMemorySize, P1_SMEM);
        cudaFuncSetAttribute(phase2_kernel,
                             cudaFuncAttributeMaxDynamicSharedMemorySize, P2_SMEM);
        attr_done = true;
    }

    prep_kernel<<<Kq, 256>>>(anchor, sraw);
    phase1_kernel<<<dim3(Nq / 256, Bq), 256, P1_SMEM>>>(x, sa_ptr);
    wsum_kernel<<<Bq * Kq, 256>>>(sa_ptr);
    sa16_kernel<<<Bq * Kq, 256>>>(sa_ptr);
    phase2_kernel<<<dim3(Cq / 256, Bq, 8), 256, P2_SMEM>>>(x, nullptr);
    phase3_kernel<<<Bq * Kq, 128>>>(anchor);
    phase4_kernel<<<Bq, 256>>>(flat_ptr);
}